// round 13
// baseline (speedup 1.0000x reference)
#include <cuda_runtime.h>
#include <cuda_fp16.h>
#include <math.h>
#include <stdint.h>

// ---------------- problem constants ----------------
#define NN 20000
#define EE 200000
#define HSZ (1u<<19)
#define HMASK (HSZ-1u)
#define NEG_ORD (-2139095041)

// ---------------- scratch ----------------
__device__ float    g_Qn[NN*256];
__device__ float    g_Vn[NN*256];
__device__ float    g_Ke[EE*256];
__device__ int      g_aggI[NN*256];
__device__ float    g_agg[NN*256];
__device__ float    g_upn[NN*256];
__device__ float    g_osum[NN*256];
__device__ float    g_isum[NN*256];
__device__ int      g_ocnt[NN];
__device__ int      g_icnt[NN];
__device__ int      g_rev[EE];
__device__ unsigned g_hkey[HSZ];
__device__ int      g_hval[HSZ];
__device__ float    g_bqp[256];
__device__ float    g_bkp[256];
// half (fp16) buffers
__device__ __half   g_upe[EE*256];
__device__ __half   g_EB[EE*768];
__device__ __half   g_EC[EE*768];
__device__ __half   g_Xa[NN*768];
__device__ __half   g_Xd[NN*768];
__device__ __half   g_xr[NN*256];
__device__ __half   g_ear[EE*256];
__device__ __half   g_hbuf[EE*768];
__device__ __half   g_cat[NN*512];
__device__ __half   g_hn[NN*512];
__device__ __half   g_twin[NN*512];
__device__ __half   g_We1h[768*1024];
__device__ __half   g_We2h[256*768];
__device__ __half   g_Wqh[256*256];
__device__ __half   g_Wkh[256*256];
__device__ __half   g_Wvh[256*256];
__device__ __half   g_Wn1h[512*512];
__device__ __half   g_Wn2h[256*512];
__device__ __half   g_Weah[256*512];

__device__ __forceinline__ int f2oi(float f){
    int i = __float_as_int(f);
    return i >= 0 ? i : i ^ 0x7FFFFFFF;
}
__device__ __forceinline__ float oi2f(int i){
    return __int_as_float(i >= 0 ? i : i ^ 0x7FFFFFFF);
}

// ---- packed fp32x2 helpers ----
__device__ __forceinline__ unsigned long long fma2(unsigned long long a,
                                                   unsigned long long b,
                                                   unsigned long long c){
    unsigned long long d;
    asm("fma.rn.f32x2 %0, %1, %2, %3;" : "=l"(d) : "l"(a), "l"(b), "l"(c));
    return d;
}
__device__ __forceinline__ unsigned long long pack2(float lo, float hi){
    unsigned long long r;
    asm("mov.b64 %0, {%1,%2};" : "=l"(r) : "f"(lo), "f"(hi));
    return r;
}
__device__ __forceinline__ void unpack2(unsigned long long v, float &lo, float &hi){
    asm("mov.b64 {%0,%1}, %2;" : "=f"(lo), "=f"(hi) : "l"(v));
}

// ---------------- init ----------------
__global__ void k_init(int N){
    int i = blockIdx.x*blockDim.x + threadIdx.x;
    if(i < (int)HSZ) g_hkey[i] = 0xFFFFFFFFu;
    if(i < N*256){ g_aggI[i] = NEG_ORD; g_osum[i] = 0.f; g_isum[i] = 0.f; }
    if(i < N){ g_ocnt[i] = 0; g_icnt[i] = 0; }
}

// ---------------- fp32 -> fp16 convert pass ----------------
__global__ void k_tohalf(const float4* __restrict__ src, uint2* __restrict__ dst, int n4){
    int i = blockIdx.x*blockDim.x + threadIdx.x;
    if(i >= n4) return;
    float4 v = src[i];
    __half2 h0 = __floats2half2_rn(v.x, v.y);
    __half2 h1 = __floats2half2_rn(v.z, v.w);
    dst[i] = make_uint2(*(unsigned*)&h0, *(unsigned*)&h1);
}

// head-major permuted weight convert for Wq/Wk: dst row n = src row (n&31)*8+(n>>5)
__global__ void k_permqk(const float* __restrict__ src, __half* __restrict__ dst){
    int i = blockIdx.x*blockDim.x + threadIdx.x;
    if(i >= 256*64) return;
    int n = i >> 6, k4 = (i & 63) << 2;
    int srow = ((n & 31) << 3) + (n >> 5);
    float4 v = *(const float4*)(src + srow*256 + k4);
    __half2 h0 = __floats2half2_rn(v.x, v.y);
    __half2 h1 = __floats2half2_rn(v.z, v.w);
    *(uint2*)(dst + n*256 + k4) = make_uint2(*(unsigned*)&h0, *(unsigned*)&h1);
}
__global__ void k_permbias(const float* __restrict__ bq, const float* __restrict__ bk){
    int n = threadIdx.x;
    int srow = ((n & 31) << 3) + (n >> 5);
    g_bqp[n] = bq[srow];
    g_bkp[n] = bk[srow];
}

// ---------------- reverse-edge hash table (+ degree counts) ----------------
__global__ void k_hash_insert(const int* __restrict__ ei, int E, int N){
    int e = blockIdx.x*blockDim.x + threadIdx.x;
    if(e >= E) return;
    unsigned key = (unsigned)ei[e] * (unsigned)N + (unsigned)ei[E+e];
    unsigned slot = ((key * 2654435761u) >> 13) & HMASK;
    while(true){
        unsigned prev = atomicCAS(&g_hkey[slot], 0xFFFFFFFFu, key);
        if(prev == 0xFFFFFFFFu){ g_hval[slot] = e; break; }
        slot = (slot + 1u) & HMASK;
    }
}

__global__ void k_rev(const int* __restrict__ ei, int E, int N){
    int e = blockIdx.x*blockDim.x + threadIdx.x;
    if(e >= E) return;
    int rr = ei[e], cc = ei[E+e];
    atomicAdd(&g_ocnt[rr], 1);
    atomicAdd(&g_icnt[cc], 1);
    unsigned rkey = (unsigned)cc * (unsigned)N + (unsigned)rr;
    unsigned slot = ((rkey * 2654435761u) >> 13) & HMASK;
    int r = -1;
    while(true){
        unsigned kk = g_hkey[slot];
        if(kk == rkey){ r = g_hval[slot]; break; }
        if(kk == 0xFFFFFFFFu) break;
        slot = (slot + 1u) & HMASK;
    }
    g_rev[e] = r;
}

// ---- fp16 TC GEMM: 128x128 block, warp tile 64x32, cp.async 4-stage ------
#define RSH 40
#define TWB (128*RSH*2)
#define STAGES 4
#define SMEM_BYTES (STAGES*2*TWB)

__device__ __forceinline__ void mma_f16(float c[4], const unsigned a[4], const unsigned b[2]){
    asm volatile(
        "mma.sync.aligned.m16n8k16.row.col.f32.f16.f16.f32 "
        "{%0,%1,%2,%3}, {%4,%5,%6,%7}, {%8,%9}, {%0,%1,%2,%3};"
        : "+f"(c[0]), "+f"(c[1]), "+f"(c[2]), "+f"(c[3])
        : "r"(a[0]), "r"(a[1]), "r"(a[2]), "r"(a[3]), "r"(b[0]), "r"(b[1]));
}
__device__ __forceinline__ void ldsm4(unsigned &r0, unsigned &r1, unsigned &r2, unsigned &r3,
                                      unsigned addr){
    asm volatile("ldmatrix.sync.aligned.m8n8.x4.shared.b16 {%0,%1,%2,%3}, [%4];"
        : "=r"(r0), "=r"(r1), "=r"(r2), "=r"(r3) : "r"(addr));
}
__device__ __forceinline__ void cp16(unsigned daddr, const void* gptr, int srcsize){
    asm volatile("cp.async.cg.shared.global [%0], [%1], 16, %2;"
        :: "r"(daddr), "l"(gptr), "r"(srcsize));
}
__device__ __forceinline__ void cp_commit(){
    asm volatile("cp.async.commit_group;" ::: "memory");
}
__device__ __forceinline__ void cp_wait2(){
    asm volatile("cp.async.wait_group 2;" ::: "memory");
}

// paired emit, one vector store per pair:
// 0: C=v(float2) ; 1: Ch=half2(relu) ; 2: C=v & C2=relu ; 3: C=relu(aux)*sigmoid(v) ;
// 4: Ch=half2(v) ; 5: Ch=half2(v) & C=float2(relu(v))
__device__ __forceinline__ void emit2(float v0, float v1, size_t idx,
                                      float* C, float* C2, __half* Ch,
                                      const float* aux, int mode){
    if(mode == 0){
        *(float2*)(C + idx) = make_float2(v0, v1);
    } else if(mode == 1){
        *(__half2*)(Ch + idx) = __floats2half2_rn(fmaxf(v0,0.f), fmaxf(v1,0.f));
    } else if(mode == 2){
        *(float2*)(C  + idx) = make_float2(v0, v1);
        *(float2*)(C2 + idx) = make_float2(fmaxf(v0,0.f), fmaxf(v1,0.f));
    } else if(mode == 3){
        float2 a = *(const float2*)(aux + idx);
        float s0 = 1.f/(1.f + __expf(-v0));
        float s1 = 1.f/(1.f + __expf(-v1));
        *(float2*)(C + idx) = make_float2(fmaxf(a.x,0.f)*s0, fmaxf(a.y,0.f)*s1);
    } else if(mode == 4){
        *(__half2*)(Ch + idx) = __floats2half2_rn(v0, v1);
    } else {
        *(__half2*)(Ch + idx) = __floats2half2_rn(v0, v1);
        *(float2*)(C + idx)   = make_float2(fmaxf(v0,0.f), fmaxf(v1,0.f));
    }
}

__global__ void __launch_bounds__(256, 2)
k_hgemm(int M, int Ncol, int K,
        const __half* __restrict__ A, int lda,
        const __half* __restrict__ W, int ldw,
        const float* __restrict__ bias,
        float* __restrict__ C, int ldc,
        float* __restrict__ C2, __half* __restrict__ Ch,
        const float* __restrict__ aux, int mode)
{
    extern __shared__ unsigned char smem_raw[];

    const int tid  = threadIdx.x;
    const int lane = tid & 31;
    const int warp = tid >> 5;
    const int tg   = lane & 3;
    const int g    = lane >> 2;
    const int bm   = blockIdx.y * 128;
    const int bn   = blockIdx.x * 128;
    const int mw   = (warp >> 2) * 64;
    const int nw   = (warp & 3) * 32;

    const unsigned sAaddr = (unsigned)__cvta_generic_to_shared(smem_raw);
    const unsigned sBaddr = sAaddr + STAGES*TWB;

    int cR[2], cK8[2];
    #pragma unroll
    for(int i=0;i<2;i++){
        int u = i*256 + tid;
        cR[i] = u >> 2; cK8[i] = (u & 3) << 3;
    }

    auto issue = [&](int kc, int buf){
        const int k0 = kc * 32;
        #pragma unroll
        for(int i=0;i<2;i++){
            unsigned doff = (unsigned)(buf*TWB + cR[i]*(RSH*2) + cK8[i]*2);
            int gm = bm + cR[i];
            const __half* srcA = A + (size_t)(gm < M ? gm : 0)*lda + k0 + cK8[i];
            cp16(sAaddr + doff, srcA, gm < M ? 16 : 0);
            const __half* srcB = W + (size_t)(bn + cR[i])*ldw + k0 + cK8[i];
            cp16(sBaddr + doff, srcB, 16);
        }
        cp_commit();
    };

    const int lr  = lane & 15;
    const int lc8 = (lane >> 4) << 3;
    unsigned aOff[4], bOff[2];
    #pragma unroll
    for(int mi=0;mi<4;mi++)  aOff[mi]  = (unsigned)(((mw + mi*16 + lr)*RSH + lc8) * 2);
    #pragma unroll
    for(int ni2=0;ni2<2;ni2++) bOff[ni2] = (unsigned)(((nw + ni2*16 + lr)*RSH + lc8) * 2);

    float acc[4][4][4];
    #pragma unroll
    for(int mi=0;mi<4;mi++)
        #pragma unroll
        for(int ni=0;ni<4;ni++)
            #pragma unroll
            for(int t=0;t<4;t++) acc[mi][ni][t] = 0.f;

    const int NC = K / 32;
    issue(0, 0); issue(1, 1); issue(2, 2);

    int buf = 0;
    for(int c=0; c<NC; c++){
        cp_wait2();
        __syncthreads();

        if (c + 3 < NC) issue(c + 3, (buf + 3) & 3);
        else            cp_commit();

        const unsigned aBase = sAaddr + (unsigned)(buf*TWB);
        const unsigned bBase = sBaddr + (unsigned)(buf*TWB);
        #pragma unroll
        for(int ks=0;ks<32;ks+=16){
            unsigned af[4][4], bf[4][2];
            #pragma unroll
            for(int mi=0;mi<4;mi++)
                ldsm4(af[mi][0], af[mi][1], af[mi][2], af[mi][3],
                      aBase + aOff[mi] + (unsigned)(ks*2));
            #pragma unroll
            for(int ni2=0;ni2<2;ni2++){
                unsigned r0,r1,r2,r3;
                ldsm4(r0, r1, r2, r3, bBase + bOff[ni2] + (unsigned)(ks*2));
                bf[ni2*2+0][0] = r0; bf[ni2*2+0][1] = r2;
                bf[ni2*2+1][0] = r1; bf[ni2*2+1][1] = r3;
            }
            #pragma unroll
            for(int mi=0;mi<4;mi++)
                #pragma unroll
                for(int ni=0;ni<4;ni++)
                    mma_f16(acc[mi][ni], af[mi], bf[ni]);
        }
        buf = (buf + 1) & 3;
    }

    // ---- epilogue (paired vector stores)
    #pragma unroll
    for(int mi=0;mi<4;mi++){
        int row0 = bm + mw + mi*16 + g;
        int row1 = row0 + 8;
        #pragma unroll
        for(int ni=0;ni<4;ni++){
            int col = bn + nw + ni*8 + tg*2;
            float b0 = bias ? bias[col]   : 0.f;
            float b1 = bias ? bias[col+1] : 0.f;
            if(row0 < M)
                emit2(acc[mi][ni][0] + b0, acc[mi][ni][1] + b1,
                      (size_t)row0*ldc + col, C, C2, Ch, aux, mode);
            if(row1 < M)
                emit2(acc[mi][ni][2] + b0, acc[mi][ni][3] + b1,
                      (size_t)row1*ldc + col, C, C2, Ch, aux, mode);
        }
    }
}

// ---------------- combine (all-fp16 buffers): h = relu(Xa[row]+EB+EC[rev]+Xd[col]+be1)
__global__ void k_combine(const int* __restrict__ ei,
                          const float* __restrict__ be1, int E){
    long long gid = (long long)blockIdx.x*blockDim.x + threadIdx.x;
    if(gid >= (long long)E*192) return;
    int e = (int)(gid/192);
    int q = (int)(gid%192);
    int j = q*4;
    int r  = ei[e], c = ei[E+e], rv = g_rev[e];

    uint2 uv  = *(const uint2*)(g_EB + (size_t)e*768 + j);
    uint2 uxa = *(const uint2*)(g_Xa + (size_t)r*768 + j);
    uint2 uxd = *(const uint2*)(g_Xd + (size_t)c*768 + j);
    float4 b  = *(const float4*)(be1 + j);

    float2 v0  = __half22float2(*(__half2*)&uv.x);
    float2 v1  = __half22float2(*(__half2*)&uv.y);
    float2 xa0 = __half22float2(*(__half2*)&uxa.x);
    float2 xa1 = __half22float2(*(__half2*)&uxa.y);
    float2 xd0 = __half22float2(*(__half2*)&uxd.x);
    float2 xd1 = __half22float2(*(__half2*)&uxd.y);

    float o0 = v0.x + xa0.x + xd0.x + b.x;
    float o1 = v0.y + xa0.y + xd0.y + b.y;
    float o2 = v1.x + xa1.x + xd1.x + b.z;
    float o3 = v1.y + xa1.y + xd1.y + b.w;
    if(rv >= 0){
        uint2 uec = *(const uint2*)(g_EC + (size_t)rv*768 + j);
        float2 e0 = __half22float2(*(__half2*)&uec.x);
        float2 e1 = __half22float2(*(__half2*)&uec.y);
        o0 += e0.x; o1 += e0.y; o2 += e1.x; o3 += e1.y;
    }
    __half2 h0 = __floats2half2_rn(fmaxf(o0,0.f), fmaxf(o1,0.f));
    __half2 h1 = __floats2half2_rn(fmaxf(o2,0.f), fmaxf(o3,0.f));
    *(uint2*)(g_hbuf + (size_t)e*768 + j) = make_uint2(*(unsigned*)&h0, *(unsigned*)&h1);
}

// ---------------- fused attention MLP (fma.f32x2) + softmax + scatter-max
// Q/K are head-major: row = node/edge, cols [h*32 .. h*32+31]
__global__ void __launch_bounds__(256)
k_attn(const int* __restrict__ ei,
       const float* __restrict__ Wa1, const float* __restrict__ ba1,
       const float* __restrict__ Wa2, const float* __restrict__ ba2,
       float* __restrict__ out_prob, int E)
{
    __shared__ ulonglong2 sW1[1024];   // Wa1 64x64 floats as packed pairs
    __shared__ ulonglong2 sW2[512];    // Wa2 32x64
    __shared__ float  sb1[64], sb2[32];
    for(int i=threadIdx.x;i<1024;i+=256) sW1[i] = ((const ulonglong2*)Wa1)[i];
    for(int i=threadIdx.x;i<512; i+=256) sW2[i] = ((const ulonglong2*)Wa2)[i];
    if(threadIdx.x < 64) sb1[threadIdx.x] = ba1[threadIdx.x];
    if(threadIdx.x < 32) sb2[threadIdx.x] = ba2[threadIdx.x];
    __syncthreads();

    long long gid = (long long)blockIdx.x*256 + threadIdx.x;
    if(gid >= (long long)E*8) return;
    int e = (int)(gid >> 3);
    int h = (int)(gid & 7);
    int r = ei[e], c = ei[E+e];

    // packed input: [q(32) | k(32)] as 32 f32x2 pairs
    unsigned long long ain2[32];
    {
        const ulonglong2* qv = (const ulonglong2*)(g_Qn + (size_t)r*256 + h*32);
        const ulonglong2* kv = (const ulonglong2*)(g_Ke + (size_t)e*256 + h*32);
        #pragma unroll
        for(int i=0;i<8;i++){
            ulonglong2 t = qv[i];
            ain2[i*2]   = t.x; ain2[i*2+1]   = t.y;
        }
        #pragma unroll
        for(int i=0;i<8;i++){
            ulonglong2 t = kv[i];
            ain2[16+i*2] = t.x; ain2[16+i*2+1] = t.y;
        }
    }

    unsigned long long attP[32];
    #pragma unroll
    for(int p=0;p<32;p++) attP[p] = 0ull;

    #pragma unroll 1
    for(int o4=0;o4<16;o4++){
        float a1v[4];
        #pragma unroll
        for(int s=0;s<4;s++){
            int o = o4*4 + s;
            unsigned long long acc = 0ull;
            #pragma unroll
            for(int c4=0;c4<16;c4++){
                ulonglong2 w = sW1[o*16 + c4];
                acc = fma2(w.x, ain2[c4*2],   acc);
                acc = fma2(w.y, ain2[c4*2+1], acc);
            }
            float lo, hi; unpack2(acc, lo, hi);
            a1v[s] = fmaxf(sb1[o] + lo + hi, 0.f);
        }
        unsigned long long a01 = pack2(a1v[0], a1v[1]);
        unsigned long long a23 = pack2(a1v[2], a1v[3]);
        #pragma unroll
        for(int p=0;p<32;p++){
            ulonglong2 w = sW2[p*16 + o4];
            attP[p] = fma2(w.x, a01, attP[p]);
            attP[p] = fma2(w.y, a23, attP[p]);
        }
    }

    float att[32];
    #pragma unroll
    for(int p=0;p<32;p++){
        float lo, hi; unpack2(attP[p], lo, hi);
        att[p] = sb2[p] + lo + hi;
    }

    const float invT = 0.17677669529663687f;
    float mx = att[0];
    #pragma unroll
    for(int p=1;p<32;p++) mx = fmaxf(mx, att[p]);
    float sum = 0.f;
    #pragma unroll
    for(int p=0;p<32;p++){ att[p] = __expf((att[p]-mx)*invT); sum += att[p]; }
    float inv = 1.f/sum;

    float* pp = out_prob + (size_t)e*256 + h;
    const float* vrow = g_Vn + (size_t)c*256 + h;
    int* ar = g_aggI + r*256 + h;
    #pragma unroll
    for(int p=0;p<32;p++){
        float pr = att[p]*inv;
        pp[p*8] = pr;
        float w = pr * vrow[p*8];
        atomicMax(ar + p*8, f2oi(w));
    }
}

// ---------------- small elementwise kernels ----------------
__global__ void k_agg_final(int N){
    int i = blockIdx.x*blockDim.x + threadIdx.x;
    if(i >= N*256) return;
    float v = oi2f(g_aggI[i]);
    g_agg[i] = isfinite(v) ? v : 0.f;
}

__global__ void k_concat(const float* __restrict__ x, int N){
    int i = blockIdx.x*blockDim.x + threadIdx.x;
    if(i >= N*512) return;
    int n = i >> 9, j = i & 511;
    float v = (j < 256) ? x[(size_t)n*256 + j] : g_agg[(size_t)n*256 + j - 256];
    g_cat[i] = __float2half_rn(v);
}

__global__ void k_twin_scatter(const int* __restrict__ ei, int E){
    long long gid = (long long)blockIdx.x*blockDim.x + threadIdx.x;
    if(gid >= (long long)E*64) return;
    int e  = (int)(gid >> 6);
    int j4 = (int)(gid & 63);
    int r = ei[e], c = ei[E+e];
    uint2 uu = *(const uint2*)(g_upe + (size_t)e*256 + j4*4);
    float2 u0 = __half22float2(*(__half2*)&uu.x);
    float2 u1 = __half22float2(*(__half2*)&uu.y);
    int base = j4*4;
    atomicAdd(&g_osum[r*256+base+0], u0.x);
    atomicAdd(&g_osum[r*256+base+1], u0.y);
    atomicAdd(&g_osum[r*256+base+2], u1.x);
    atomicAdd(&g_osum[r*256+base+3], u1.y);
    atomicAdd(&g_isum[c*256+base+0], u0.x);
    atomicAdd(&g_isum[c*256+base+1], u0.y);
    atomicAdd(&g_isum[c*256+base+2], u1.x);
    atomicAdd(&g_isum[c*256+base+3], u1.y);
}

__global__ void k_twin_final(int N){
    int i = blockIdx.x*blockDim.x + threadIdx.x;
    if(i >= N*512) return;
    int n = i >> 9, j = i & 511;
    float v;
    if(j < 256) v = g_osum[n*256 + j]       / fmaxf((float)g_ocnt[n], 1.f);
    else        v = g_isum[n*256 + j - 256] / fmaxf((float)g_icnt[n], 1.f);
    g_twin[i] = __float2half_rn(v);
}

// ---------------- launcher ----------------
extern "C" void kernel_launch(void* const* d_in, const int* in_sizes, int n_in,
                              void* d_out, int out_size)
{
    const float* x   = (const float*)d_in[0];
    const float* ea  = (const float*)d_in[1];
    const float* Wq  = (const float*)d_in[2];
    const float* bq  = (const float*)d_in[3];
    const float* Wk  = (const float*)d_in[4];
    const float* bk  = (const float*)d_in[5];
    const float* Wv  = (const float*)d_in[6];
    const float* bv  = (const float*)d_in[7];
    const float* We1 = (const float*)d_in[8];
    const float* be1 = (const float*)d_in[9];
    const float* We2 = (const float*)d_in[10];
    const float* be2 = (const float*)d_in[11];
    const float* Wea = (const float*)d_in[12];
    const float* bea = (const float*)d_in[13];
    const float* Wn1 = (const float*)d_in[14];
    const float* bn1 = (const float*)d_in[15];
    const float* Wn2 = (const float*)d_in[16];
    const float* bn2 = (const float*)d_in[17];
    const float* Wa1 = (const float*)d_in[18];
    const float* ba1 = (const float*)d_in[19];
    const float* Wa2 = (const float*)d_in[20];
    const float* ba2 = (const float*)d_in[21];
    const int*   ei  = (const int*)  d_in[22];

    const int N = in_sizes[0]/256;
    const int E = in_sizes[1]/256;

    float* out      = (float*)d_out;
    float* out_node = out;
    float* out_edge = out + (size_t)N*256;
    float* out_prob = out_edge + (size_t)E*256;

    void* p;
    #define GSYMF(v, s) float* v; cudaGetSymbolAddress(&p, s); v = (float*)p;
    #define GSYMH(v, s) __half* v; cudaGetSymbolAddress(&p, s); v = (__half*)p;
    GSYMF(pQ,   g_Qn)  GSYMF(pV,   g_Vn)  GSYMF(pK,  g_Ke)
    GSYMF(pUpn, g_upn)
    GSYMF(pBqp, g_bqp) GSYMF(pBkp, g_bkp)
    GSYMH(pUPE, g_upe)
    GSYMH(pXa,  g_Xa)  GSYMH(pXd,  g_Xd)  GSYMH(pEB, g_EB) GSYMH(pEC, g_EC)
    GSYMH(pH,   g_hbuf)
    GSYMH(pCat, g_cat) GSYMH(pHn, g_hn)  GSYMH(pTwin, g_twin)
    GSYMH(pXr,  g_xr)  GSYMH(pEar, g_ear)
    GSYMH(pWe1h, g_We1h) GSYMH(pWe2h, g_We2h)
    GSYMH(pWqh, g_Wqh) GSYMH(pWkh, g_Wkh) GSYMH(pWvh, g_Wvh)
    GSYMH(pWn1h, g_Wn1h) GSYMH(pWn2h, g_Wn2h) GSYMH(pWeah, g_Weah)
    #undef GSYMF
    #undef GSYMH

    cudaFuncSetAttribute(k_hgemm, cudaFuncAttributeMaxDynamicSharedMemorySize, SMEM_BYTES);

    auto H = [&](const float* src, __half* dst, int n){
        k_tohalf<<<(n/4 + 255)/256, 256>>>((const float4*)src, (uint2*)dst, n/4);
    };
    H(x,   pXr,   N*256);
    H(ea,  pEar,  E*256);
    H(We1, pWe1h, 768*1024);
    H(We2, pWe2h, 256*768);
    H(Wv,  pWvh,  256*256);
    H(Wn1, pWn1h, 512*512);
    H(Wn2, pWn2h, 256*512);
    H(Wea, pWeah, 256*512);
    // head-major permuted Wq/Wk + biases
    k_permqk<<<(256*64 + 255)/256, 256>>>(Wq, pWqh);
    k_permqk<<<(256*64 + 255)/256, 256>>>(Wk, pWkh);
    k_permbias<<<1, 256>>>(bq, bk);

    k_init<<<(NN*256+255)/256, 256>>>(N);
    k_hash_insert<<<(E+255)/256, 256>>>(ei, E, N);
    k_rev<<<(E+255)/256, 256>>>(ei, E, N);

    auto GEMM = [&](int M, int Nc, int K, const __half* A, int lda,
                    const __half* W, int ldw, const float* bias,
                    float* C, int ldc, float* C2, __half* Ch,
                    const float* aux, int mode){
        dim3 g(Nc/128, (M+127)/128);
        k_hgemm<<<g, 256, SMEM_BYTES>>>(M, Nc, K, A, lda, W, ldw, bias,
                                        C, ldc, C2, Ch, aux, mode);
    };

    // edge-update MLP, factored by We1 column blocks (half outputs)
    GEMM(N, 768, 256, pXr,  256, pWe1h + 0,   1024, nullptr, nullptr, 768, nullptr, pXa, nullptr, 4);
    GEMM(N, 768, 256, pXr,  256, pWe1h + 768, 1024, nullptr, nullptr, 768, nullptr, pXd, nullptr, 4);
    GEMM(E, 768, 256, pEar, 256, pWe1h + 256, 1024, nullptr, nullptr, 768, nullptr, pEB, nullptr, 4);
    GEMM(E, 768, 256, pEar, 256, pWe1h + 512, 1024, nullptr, nullptr, 768, nullptr, pEC, nullptr, 4);
    k_combine<<<(int)(((long long)E*192 + 255)/256), 256>>>(ei, be1, E);
    // mode 5: upe half + out_edge relu fp32
    GEMM(E, 256, 768, pH, 768, pWe2h, 768, be2, out_edge, 256, nullptr, pUPE, nullptr, 5);

    // q/k head-major (permuted weights+bias), v standard
    GEMM(N, 256, 256, pXr,  256, pWqh, 256, pBqp, pQ, 256, nullptr, nullptr, nullptr, 0);
    GEMM(N, 256, 256, pXr,  256, pWvh, 256, bv,   pV, 256, nullptr, nullptr, nullptr, 0);
    GEMM(E, 256, 256, pEar, 256, pWkh, 256, pBkp, pK, 256, nullptr, nullptr, nullptr, 0);

    // attention + scatter-max aggregation
    k_attn<<<(int)(((long long)E*8 + 255)/256), 256>>>(ei, Wa1, ba1, Wa2, ba2, out_prob, E);
    k_agg_final<<<(NN*256+255)/256, 256>>>(N);

    // node update MLP
    k_concat<<<(NN*512+255)/256, 256>>>(x, N);
    GEMM(N, 512, 512, pCat, 512, pWn1h, 512, bn1, nullptr, 512, nullptr, pHn, nullptr, 1);
    GEMM(N, 256, 512, pHn,  512, pWn2h, 512, bn2, pUpn, 256, nullptr, nullptr, nullptr, 0);

    // twin aggregation + gated output
    k_twin_scatter<<<(int)(((long long)E*64 + 255)/256), 256>>>(ei, E);
    k_twin_final<<<(NN*512+255)/256, 256>>>(N);
    GEMM(N, 256, 512, pTwin, 512, pWeah, 512, bea, out_node, 256, nullptr, nullptr, pUpn, 3);
}

// round 14
// speedup vs baseline: 1.0013x; 1.0013x over previous
#include <cuda_runtime.h>
#include <cuda_fp16.h>
#include <math.h>
#include <stdint.h>

// ---------------- problem constants ----------------
#define NN 20000
#define EE 200000
#define HSZ (1u<<19)
#define HMASK (HSZ-1u)
#define NEG_ORD (-2139095041)

// ---------------- scratch ----------------
__device__ float    g_Qn[NN*256];
__device__ float    g_Vn[NN*256];
__device__ float    g_Ke[EE*256];
__device__ int      g_aggI[NN*256];
__device__ float    g_agg[NN*256];
__device__ float    g_upn[NN*256];
__device__ float    g_osum[NN*256];
__device__ float    g_isum[NN*256];
__device__ int      g_ocnt[NN];
__device__ int      g_icnt[NN];
__device__ int      g_rev[EE];
__device__ unsigned g_hkey[HSZ];
__device__ int      g_hval[HSZ];
// half (fp16) buffers
__device__ __half   g_upe[EE*256];
__device__ __half   g_EB[EE*768];
__device__ __half   g_EC[EE*768];
__device__ __half   g_Xa[NN*768];
__device__ __half   g_Xd[NN*768];
__device__ __half   g_xr[NN*256];
__device__ __half   g_ear[EE*256];
__device__ __half   g_hbuf[EE*768];
__device__ __half   g_cat[NN*512];
__device__ __half   g_hn[NN*512];
__device__ __half   g_twin[NN*512];
__device__ __half   g_We1h[768*1024];
__device__ __half   g_We2h[256*768];
__device__ __half   g_Wqh[256*256];
__device__ __half   g_Wkh[256*256];
__device__ __half   g_Wvh[256*256];
__device__ __half   g_Wn1h[512*512];
__device__ __half   g_Wn2h[256*512];
__device__ __half   g_Weah[256*512];

__device__ __forceinline__ int f2oi(float f){
    int i = __float_as_int(f);
    return i >= 0 ? i : i ^ 0x7FFFFFFF;
}
__device__ __forceinline__ float oi2f(int i){
    return __int_as_float(i >= 0 ? i : i ^ 0x7FFFFFFF);
}

// ---- packed fp32x2 helpers ----
__device__ __forceinline__ unsigned long long fma2(unsigned long long a,
                                                   unsigned long long b,
                                                   unsigned long long c){
    unsigned long long d;
    asm("fma.rn.f32x2 %0, %1, %2, %3;" : "=l"(d) : "l"(a), "l"(b), "l"(c));
    return d;
}
__device__ __forceinline__ unsigned long long pack2(float lo, float hi){
    unsigned long long r;
    asm("mov.b64 %0, {%1,%2};" : "=l"(r) : "f"(lo), "f"(hi));
    return r;
}
__device__ __forceinline__ void unpack2(unsigned long long v, float &lo, float &hi){
    asm("mov.b64 {%0,%1}, %2;" : "=f"(lo), "=f"(hi) : "l"(v));
}

// ---------------- init ----------------
__global__ void k_init(int N){
    int i = blockIdx.x*blockDim.x + threadIdx.x;
    if(i < (int)HSZ) g_hkey[i] = 0xFFFFFFFFu;
    if(i < N*256){ g_aggI[i] = NEG_ORD; g_osum[i] = 0.f; g_isum[i] = 0.f; }
    if(i < N){ g_ocnt[i] = 0; g_icnt[i] = 0; }
}

// ---------------- fp32 -> fp16 convert pass ----------------
__global__ void k_tohalf(const float4* __restrict__ src, uint2* __restrict__ dst, int n4){
    int i = blockIdx.x*blockDim.x + threadIdx.x;
    if(i >= n4) return;
    float4 v = src[i];
    __half2 h0 = __floats2half2_rn(v.x, v.y);
    __half2 h1 = __floats2half2_rn(v.z, v.w);
    dst[i] = make_uint2(*(unsigned*)&h0, *(unsigned*)&h1);
}

// ---------------- reverse-edge hash table (+ degree counts) ----------------
__global__ void k_hash_insert(const int* __restrict__ ei, int E, int N){
    int e = blockIdx.x*blockDim.x + threadIdx.x;
    if(e >= E) return;
    unsigned key = (unsigned)ei[e] * (unsigned)N + (unsigned)ei[E+e];
    unsigned slot = ((key * 2654435761u) >> 13) & HMASK;
    while(true){
        unsigned prev = atomicCAS(&g_hkey[slot], 0xFFFFFFFFu, key);
        if(prev == 0xFFFFFFFFu){ g_hval[slot] = e; break; }
        slot = (slot + 1u) & HMASK;
    }
}

__global__ void k_rev(const int* __restrict__ ei, int E, int N){
    int e = blockIdx.x*blockDim.x + threadIdx.x;
    if(e >= E) return;
    int rr = ei[e], cc = ei[E+e];
    atomicAdd(&g_ocnt[rr], 1);
    atomicAdd(&g_icnt[cc], 1);
    unsigned rkey = (unsigned)cc * (unsigned)N + (unsigned)rr;
    unsigned slot = ((rkey * 2654435761u) >> 13) & HMASK;
    int r = -1;
    while(true){
        unsigned kk = g_hkey[slot];
        if(kk == rkey){ r = g_hval[slot]; break; }
        if(kk == 0xFFFFFFFFu) break;
        slot = (slot + 1u) & HMASK;
    }
    g_rev[e] = r;
}

// ---- fp16 TC GEMM: 128x128 block, warp tile 64x32, cp.async 4-stage ------
#define RSH 40
#define TWB (128*RSH*2)
#define STAGES 4
#define SMEM_BYTES (STAGES*2*TWB)

__device__ __forceinline__ void mma_f16(float c[4], const unsigned a[4], const unsigned b[2]){
    asm volatile(
        "mma.sync.aligned.m16n8k16.row.col.f32.f16.f16.f32 "
        "{%0,%1,%2,%3}, {%4,%5,%6,%7}, {%8,%9}, {%0,%1,%2,%3};"
        : "+f"(c[0]), "+f"(c[1]), "+f"(c[2]), "+f"(c[3])
        : "r"(a[0]), "r"(a[1]), "r"(a[2]), "r"(a[3]), "r"(b[0]), "r"(b[1]));
}
__device__ __forceinline__ void ldsm4(unsigned &r0, unsigned &r1, unsigned &r2, unsigned &r3,
                                      unsigned addr){
    asm volatile("ldmatrix.sync.aligned.m8n8.x4.shared.b16 {%0,%1,%2,%3}, [%4];"
        : "=r"(r0), "=r"(r1), "=r"(r2), "=r"(r3) : "r"(addr));
}
__device__ __forceinline__ void cp16(unsigned daddr, const void* gptr, int srcsize){
    asm volatile("cp.async.cg.shared.global [%0], [%1], 16, %2;"
        :: "r"(daddr), "l"(gptr), "r"(srcsize));
}
__device__ __forceinline__ void cp_commit(){
    asm volatile("cp.async.commit_group;" ::: "memory");
}
__device__ __forceinline__ void cp_wait2(){
    asm volatile("cp.async.wait_group 2;" ::: "memory");
}

// paired emit, one vector store per pair:
// 0: C=v(float2) ; 1: Ch=half2(relu) ; 2: C=v & C2=relu ; 3: C=relu(aux)*sigmoid(v) ;
// 4: Ch=half2(v) ; 5: Ch=half2(v) & C=float2(relu(v))
__device__ __forceinline__ void emit2(float v0, float v1, size_t idx,
                                      float* C, float* C2, __half* Ch,
                                      const float* aux, int mode){
    if(mode == 0){
        *(float2*)(C + idx) = make_float2(v0, v1);
    } else if(mode == 1){
        *(__half2*)(Ch + idx) = __floats2half2_rn(fmaxf(v0,0.f), fmaxf(v1,0.f));
    } else if(mode == 2){
        *(float2*)(C  + idx) = make_float2(v0, v1);
        *(float2*)(C2 + idx) = make_float2(fmaxf(v0,0.f), fmaxf(v1,0.f));
    } else if(mode == 3){
        float2 a = *(const float2*)(aux + idx);
        float s0 = 1.f/(1.f + __expf(-v0));
        float s1 = 1.f/(1.f + __expf(-v1));
        *(float2*)(C + idx) = make_float2(fmaxf(a.x,0.f)*s0, fmaxf(a.y,0.f)*s1);
    } else if(mode == 4){
        *(__half2*)(Ch + idx) = __floats2half2_rn(v0, v1);
    } else {
        *(__half2*)(Ch + idx) = __floats2half2_rn(v0, v1);
        *(float2*)(C + idx)   = make_float2(fmaxf(v0,0.f), fmaxf(v1,0.f));
    }
}

__global__ void __launch_bounds__(256, 2)
k_hgemm(int M, int Ncol, int K,
        const __half* __restrict__ A, int lda,
        const __half* __restrict__ W, int ldw,
        const float* __restrict__ bias,
        float* __restrict__ C, int ldc,
        float* __restrict__ C2, __half* __restrict__ Ch,
        const float* __restrict__ aux, int mode)
{
    extern __shared__ unsigned char smem_raw[];

    const int tid  = threadIdx.x;
    const int lane = tid & 31;
    const int warp = tid >> 5;
    const int tg   = lane & 3;
    const int g    = lane >> 2;
    const int bm   = blockIdx.y * 128;
    const int bn   = blockIdx.x * 128;
    const int mw   = (warp >> 2) * 64;
    const int nw   = (warp & 3) * 32;

    const unsigned sAaddr = (unsigned)__cvta_generic_to_shared(smem_raw);
    const unsigned sBaddr = sAaddr + STAGES*TWB;

    int cR[2], cK8[2];
    #pragma unroll
    for(int i=0;i<2;i++){
        int u = i*256 + tid;
        cR[i] = u >> 2; cK8[i] = (u & 3) << 3;
    }

    auto issue = [&](int kc, int buf){
        const int k0 = kc * 32;
        #pragma unroll
        for(int i=0;i<2;i++){
            unsigned doff = (unsigned)(buf*TWB + cR[i]*(RSH*2) + cK8[i]*2);
            int gm = bm + cR[i];
            const __half* srcA = A + (size_t)(gm < M ? gm : 0)*lda + k0 + cK8[i];
            cp16(sAaddr + doff, srcA, gm < M ? 16 : 0);
            const __half* srcB = W + (size_t)(bn + cR[i])*ldw + k0 + cK8[i];
            cp16(sBaddr + doff, srcB, 16);
        }
        cp_commit();
    };

    const int lr  = lane & 15;
    const int lc8 = (lane >> 4) << 3;
    unsigned aOff[4], bOff[2];
    #pragma unroll
    for(int mi=0;mi<4;mi++)  aOff[mi]  = (unsigned)(((mw + mi*16 + lr)*RSH + lc8) * 2);
    #pragma unroll
    for(int ni2=0;ni2<2;ni2++) bOff[ni2] = (unsigned)(((nw + ni2*16 + lr)*RSH + lc8) * 2);

    float acc[4][4][4];
    #pragma unroll
    for(int mi=0;mi<4;mi++)
        #pragma unroll
        for(int ni=0;ni<4;ni++)
            #pragma unroll
            for(int t=0;t<4;t++) acc[mi][ni][t] = 0.f;

    const int NC = K / 32;
    issue(0, 0); issue(1, 1); issue(2, 2);

    int buf = 0;
    for(int c=0; c<NC; c++){
        cp_wait2();
        __syncthreads();

        if (c + 3 < NC) issue(c + 3, (buf + 3) & 3);
        else            cp_commit();

        const unsigned aBase = sAaddr + (unsigned)(buf*TWB);
        const unsigned bBase = sBaddr + (unsigned)(buf*TWB);
        #pragma unroll
        for(int ks=0;ks<32;ks+=16){
            unsigned af[4][4], bf[4][2];
            #pragma unroll
            for(int mi=0;mi<4;mi++)
                ldsm4(af[mi][0], af[mi][1], af[mi][2], af[mi][3],
                      aBase + aOff[mi] + (unsigned)(ks*2));
            #pragma unroll
            for(int ni2=0;ni2<2;ni2++){
                unsigned r0,r1,r2,r3;
                ldsm4(r0, r1, r2, r3, bBase + bOff[ni2] + (unsigned)(ks*2));
                bf[ni2*2+0][0] = r0; bf[ni2*2+0][1] = r2;
                bf[ni2*2+1][0] = r1; bf[ni2*2+1][1] = r3;
            }
            #pragma unroll
            for(int mi=0;mi<4;mi++)
                #pragma unroll
                for(int ni=0;ni<4;ni++)
                    mma_f16(acc[mi][ni], af[mi], bf[ni]);
        }
        buf = (buf + 1) & 3;
    }

    // ---- epilogue (paired vector stores)
    #pragma unroll
    for(int mi=0;mi<4;mi++){
        int row0 = bm + mw + mi*16 + g;
        int row1 = row0 + 8;
        #pragma unroll
        for(int ni=0;ni<4;ni++){
            int col = bn + nw + ni*8 + tg*2;
            float b0 = bias ? bias[col]   : 0.f;
            float b1 = bias ? bias[col+1] : 0.f;
            if(row0 < M)
                emit2(acc[mi][ni][0] + b0, acc[mi][ni][1] + b1,
                      (size_t)row0*ldc + col, C, C2, Ch, aux, mode);
            if(row1 < M)
                emit2(acc[mi][ni][2] + b0, acc[mi][ni][3] + b1,
                      (size_t)row1*ldc + col, C, C2, Ch, aux, mode);
        }
    }
}

// ---------------- combine (all-fp16 buffers): h = relu(Xa[row]+EB+EC[rev]+Xd[col]+be1)
__global__ void k_combine(const int* __restrict__ ei,
                          const float* __restrict__ be1, int E){
    long long gid = (long long)blockIdx.x*blockDim.x + threadIdx.x;
    if(gid >= (long long)E*192) return;
    int e = (int)(gid/192);
    int q = (int)(gid%192);
    int j = q*4;
    int r  = ei[e], c = ei[E+e], rv = g_rev[e];

    uint2 uv  = *(const uint2*)(g_EB + (size_t)e*768 + j);
    uint2 uxa = *(const uint2*)(g_Xa + (size_t)r*768 + j);
    uint2 uxd = *(const uint2*)(g_Xd + (size_t)c*768 + j);
    float4 b  = *(const float4*)(be1 + j);

    float2 v0  = __half22float2(*(__half2*)&uv.x);
    float2 v1  = __half22float2(*(__half2*)&uv.y);
    float2 xa0 = __half22float2(*(__half2*)&uxa.x);
    float2 xa1 = __half22float2(*(__half2*)&uxa.y);
    float2 xd0 = __half22float2(*(__half2*)&uxd.x);
    float2 xd1 = __half22float2(*(__half2*)&uxd.y);

    float o0 = v0.x + xa0.x + xd0.x + b.x;
    float o1 = v0.y + xa0.y + xd0.y + b.y;
    float o2 = v1.x + xa1.x + xd1.x + b.z;
    float o3 = v1.y + xa1.y + xd1.y + b.w;
    if(rv >= 0){
        uint2 uec = *(const uint2*)(g_EC + (size_t)rv*768 + j);
        float2 e0 = __half22float2(*(__half2*)&uec.x);
        float2 e1 = __half22float2(*(__half2*)&uec.y);
        o0 += e0.x; o1 += e0.y; o2 += e1.x; o3 += e1.y;
    }
    __half2 h0 = __floats2half2_rn(fmaxf(o0,0.f), fmaxf(o1,0.f));
    __half2 h1 = __floats2half2_rn(fmaxf(o2,0.f), fmaxf(o3,0.f));
    *(uint2*)(g_hbuf + (size_t)e*768 + j) = make_uint2(*(unsigned*)&h0, *(unsigned*)&h1);
}

// ---------------- fused attention MLP + softmax + scatter-max
// Layer 1: inputs packed over c-pairs (ain2 u64), scalar a1v outputs.
// Layer 2: outputs packed over p-pairs (attP2[16] u64), a1v broadcast.
__global__ void __launch_bounds__(256)
k_attn(const int* __restrict__ ei,
       const float* __restrict__ Wa1, const float* __restrict__ ba1,
       const float* __restrict__ Wa2, const float* __restrict__ ba2,
       float* __restrict__ out_prob, int E)
{
    __shared__ ulonglong2 sW1[1024];              // Wa1: input-pair packed, [o][c2] x2
    __shared__ unsigned long long sW2p[1024];     // Wa2: output-pair packed [p2][o]
    __shared__ float  sb1[64], sb2[32];
    for(int i=threadIdx.x;i<1024;i+=256) sW1[i] = ((const ulonglong2*)Wa1)[i];
    for(int i=threadIdx.x;i<1024;i+=256){
        int p2 = i >> 6, o = i & 63;
        sW2p[i] = pack2(Wa2[(2*p2)*64 + o], Wa2[(2*p2+1)*64 + o]);
    }
    if(threadIdx.x < 64) sb1[threadIdx.x] = ba1[threadIdx.x];
    if(threadIdx.x < 32) sb2[threadIdx.x] = ba2[threadIdx.x];
    __syncthreads();

    long long gid = (long long)blockIdx.x*256 + threadIdx.x;
    if(gid >= (long long)E*8) return;
    int e = (int)(gid >> 3);
    int h = (int)(gid & 7);
    int r = ei[e], c = ei[E+e];

    // load q/k (strided per head) and pack c-pairs
    unsigned long long ain2[32];
    {
        const float* qrow = g_Qn + (size_t)r*256 + h;
        const float* krow = g_Ke + (size_t)e*256 + h;
        #pragma unroll
        for(int i=0;i<16;i++) ain2[i]    = pack2(qrow[(2*i)*8], qrow[(2*i+1)*8]);
        #pragma unroll
        for(int i=0;i<16;i++) ain2[16+i] = pack2(krow[(2*i)*8], krow[(2*i+1)*8]);
    }

    unsigned long long attP2[16];
    #pragma unroll
    for(int p2=0;p2<16;p2++) attP2[p2] = 0ull;

    #pragma unroll 1
    for(int o4=0;o4<16;o4++){
        float a1v[4];
        #pragma unroll
        for(int s=0;s<4;s++){
            int o = o4*4 + s;
            unsigned long long acc = 0ull;
            #pragma unroll
            for(int c4=0;c4<16;c4++){
                ulonglong2 w = sW1[o*16 + c4];
                acc = fma2(w.x, ain2[c4*2],   acc);
                acc = fma2(w.y, ain2[c4*2+1], acc);
            }
            float lo, hi; unpack2(acc, lo, hi);
            a1v[s] = fmaxf(sb1[o] + lo + hi, 0.f);
        }
        #pragma unroll
        for(int s=0;s<4;s++){
            int o = o4*4 + s;
            unsigned long long ab = pack2(a1v[s], a1v[s]);
            #pragma unroll
            for(int p2=0;p2<16;p2++)
                attP2[p2] = fma2(sW2p[p2*64 + o], ab, attP2[p2]);
        }
    }

    float att[32];
    #pragma unroll
    for(int p2=0;p2<16;p2++){
        float lo, hi; unpack2(attP2[p2], lo, hi);
        att[2*p2]   = sb2[2*p2]   + lo;
        att[2*p2+1] = sb2[2*p2+1] + hi;
    }

    const float invT = 0.17677669529663687f;
    float mx = att[0];
    #pragma unroll
    for(int p=1;p<32;p++) mx = fmaxf(mx, att[p]);
    float sum = 0.f;
    #pragma unroll
    for(int p=0;p<32;p++){ att[p] = __expf((att[p]-mx)*invT); sum += att[p]; }
    float inv = 1.f/sum;

    float* pp = out_prob + (size_t)e*256 + h;
    const float* vrow = g_Vn + (size_t)c*256 + h;
    int* ar = g_aggI + r*256 + h;
    #pragma unroll
    for(int p=0;p<32;p++){
        float pr = att[p]*inv;
        pp[p*8] = pr;
        float w = pr * vrow[p*8];
        atomicMax(ar + p*8, f2oi(w));
    }
}

// ---------------- small elementwise kernels ----------------
__global__ void k_agg_final(int N){
    int i = blockIdx.x*blockDim.x + threadIdx.x;
    if(i >= N*256) return;
    float v = oi2f(g_aggI[i]);
    g_agg[i] = isfinite(v) ? v : 0.f;
}

__global__ void k_concat(const float* __restrict__ x, int N){
    int i = blockIdx.x*blockDim.x + threadIdx.x;
    if(i >= N*512) return;
    int n = i >> 9, j = i & 511;
    float v = (j < 256) ? x[(size_t)n*256 + j] : g_agg[(size_t)n*256 + j - 256];
    g_cat[i] = __float2half_rn(v);
}

__global__ void k_twin_scatter(const int* __restrict__ ei, int E){
    long long gid = (long long)blockIdx.x*blockDim.x + threadIdx.x;
    if(gid >= (long long)E*64) return;
    int e  = (int)(gid >> 6);
    int j4 = (int)(gid & 63);
    int r = ei[e], c = ei[E+e];
    uint2 uu = *(const uint2*)(g_upe + (size_t)e*256 + j4*4);
    float2 u0 = __half22float2(*(__half2*)&uu.x);
    float2 u1 = __half22float2(*(__half2*)&uu.y);
    int base = j4*4;
    atomicAdd(&g_osum[r*256+base+0], u0.x);
    atomicAdd(&g_osum[r*256+base+1], u0.y);
    atomicAdd(&g_osum[r*256+base+2], u1.x);
    atomicAdd(&g_osum[r*256+base+3], u1.y);
    atomicAdd(&g_isum[c*256+base+0], u0.x);
    atomicAdd(&g_isum[c*256+base+1], u0.y);
    atomicAdd(&g_isum[c*256+base+2], u1.x);
    atomicAdd(&g_isum[c*256+base+3], u1.y);
}

__global__ void k_twin_final(int N){
    int i = blockIdx.x*blockDim.x + threadIdx.x;
    if(i >= N*512) return;
    int n = i >> 9, j = i & 511;
    float v;
    if(j < 256) v = g_osum[n*256 + j]       / fmaxf((float)g_ocnt[n], 1.f);
    else        v = g_isum[n*256 + j - 256] / fmaxf((float)g_icnt[n], 1.f);
    g_twin[i] = __float2half_rn(v);
}

// ---------------- launcher ----------------
extern "C" void kernel_launch(void* const* d_in, const int* in_sizes, int n_in,
                              void* d_out, int out_size)
{
    const float* x   = (const float*)d_in[0];
    const float* ea  = (const float*)d_in[1];
    const float* Wq  = (const float*)d_in[2];
    const float* bq  = (const float*)d_in[3];
    const float* Wk  = (const float*)d_in[4];
    const float* bk  = (const float*)d_in[5];
    const float* Wv  = (const float*)d_in[6];
    const float* bv  = (const float*)d_in[7];
    const float* We1 = (const float*)d_in[8];
    const float* be1 = (const float*)d_in[9];
    const float* We2 = (const float*)d_in[10];
    const float* be2 = (const float*)d_in[11];
    const float* Wea = (const float*)d_in[12];
    const float* bea = (const float*)d_in[13];
    const float* Wn1 = (const float*)d_in[14];
    const float* bn1 = (const float*)d_in[15];
    const float* Wn2 = (const float*)d_in[16];
    const float* bn2 = (const float*)d_in[17];
    const float* Wa1 = (const float*)d_in[18];
    const float* ba1 = (const float*)d_in[19];
    const float* Wa2 = (const float*)d_in[20];
    const float* ba2 = (const float*)d_in[21];
    const int*   ei  = (const int*)  d_in[22];

    const int N = in_sizes[0]/256;
    const int E = in_sizes[1]/256;

    float* out      = (float*)d_out;
    float* out_node = out;
    float* out_edge = out + (size_t)N*256;
    float* out_prob = out_edge + (size_t)E*256;

    void* p;
    #define GSYMF(v, s) float* v; cudaGetSymbolAddress(&p, s); v = (float*)p;
    #define GSYMH(v, s) __half* v; cudaGetSymbolAddress(&p, s); v = (__half*)p;
    GSYMF(pQ,   g_Qn)  GSYMF(pV,   g_Vn)  GSYMF(pK,  g_Ke)
    GSYMF(pUpn, g_upn)
    GSYMH(pUPE, g_upe)
    GSYMH(pXa,  g_Xa)  GSYMH(pXd,  g_Xd)  GSYMH(pEB, g_EB) GSYMH(pEC, g_EC)
    GSYMH(pH,   g_hbuf)
    GSYMH(pCat, g_cat) GSYMH(pHn, g_hn)  GSYMH(pTwin, g_twin)
    GSYMH(pXr,  g_xr)  GSYMH(pEar, g_ear)
    GSYMH(pWe1h, g_We1h) GSYMH(pWe2h, g_We2h)
    GSYMH(pWqh, g_Wqh) GSYMH(pWkh, g_Wkh) GSYMH(pWvh, g_Wvh)
    GSYMH(pWn1h, g_Wn1h) GSYMH(pWn2h, g_Wn2h) GSYMH(pWeah, g_Weah)
    #undef GSYMF
    #undef GSYMH

    cudaFuncSetAttribute(k_hgemm, cudaFuncAttributeMaxDynamicSharedMemorySize, SMEM_BYTES);

    auto H = [&](const float* src, __half* dst, int n){
        k_tohalf<<<(n/4 + 255)/256, 256>>>((const float4*)src, (uint2*)dst, n/4);
    };
    H(x,   pXr,   N*256);
    H(ea,  pEar,  E*256);
    H(We1, pWe1h, 768*1024);
    H(We2, pWe2h, 256*768);
    H(Wq,  pWqh,  256*256);
    H(Wk,  pWkh,  256*256);
    H(Wv,  pWvh,  256*256);
    H(Wn1, pWn1h, 512*512);
    H(Wn2, pWn2h, 256*512);
    H(Wea, pWeah, 256*512);

    k_init<<<(NN*256+255)/256, 256>>>(N);
    k_hash_insert<<<(E+255)/256, 256>>>(ei, E, N);
    k_rev<<<(E+255)/256, 256>>>(ei, E, N);

    auto GEMM = [&](int M, int Nc, int K, const __half* A, int lda,
                    const __half* W, int ldw, const float* bias,
                    float* C, int ldc, float* C2, __half* Ch,
                    const float* aux, int mode){
        dim3 g(Nc/128, (M+127)/128);
        k_hgemm<<<g, 256, SMEM_BYTES>>>(M, Nc, K, A, lda, W, ldw, bias,
                                        C, ldc, C2, Ch, aux, mode);
    };

    // edge-update MLP, factored by We1 column blocks (half outputs)
    GEMM(N, 768, 256, pXr,  256, pWe1h + 0,   1024, nullptr, nullptr, 768, nullptr, pXa, nullptr, 4);
    GEMM(N, 768, 256, pXr,  256, pWe1h + 768, 1024, nullptr, nullptr, 768, nullptr, pXd, nullptr, 4);
    GEMM(E, 768, 256, pEar, 256, pWe1h + 256, 1024, nullptr, nullptr, 768, nullptr, pEB, nullptr, 4);
    GEMM(E, 768, 256, pEar, 256, pWe1h + 512, 1024, nullptr, nullptr, 768, nullptr, pEC, nullptr, 4);
    k_combine<<<(int)(((long long)E*192 + 255)/256), 256>>>(ei, be1, E);
    // mode 5: upe half + out_edge relu fp32
    GEMM(E, 256, 768, pH, 768, pWe2h, 768, be2, out_edge, 256, nullptr, pUPE, nullptr, 5);

    // q/v per node, k per edge
    GEMM(N, 256, 256, pXr,  256, pWqh, 256, bq, pQ, 256, nullptr, nullptr, nullptr, 0);
    GEMM(N, 256, 256, pXr,  256, pWvh, 256, bv, pV, 256, nullptr, nullptr, nullptr, 0);
    GEMM(E, 256, 256, pEar, 256, pWkh, 256, bk, pK, 256, nullptr, nullptr, nullptr, 0);

    // attention + scatter-max aggregation
    k_attn<<<(int)(((long long)E*8 + 255)/256), 256>>>(ei, Wa1, ba1, Wa2, ba2, out_prob, E);
    k_agg_final<<<(NN*256+255)/256, 256>>>(N);

    // node update MLP
    k_concat<<<(NN*512+255)/256, 256>>>(x, N);
    GEMM(N, 512, 512, pCat, 512, pWn1h, 512, bn1, nullptr, 512, nullptr, pHn, nullptr, 1);
    GEMM(N, 256, 512, pHn,  512, pWn2h, 512, bn2, pUpn, 256, nullptr, nullptr, nullptr, 0);

    // twin aggregation + gated output
    k_twin_scatter<<<(int)(((long long)E*64 + 255)/256), 256>>>(ei, E);
    k_twin_final<<<(NN*512+255)/256, 256>>>(N);
    GEMM(N, 256, 512, pTwin, 512, pWeah, 512, bea, out_node, 256, nullptr, nullptr, pUpn, 3);
}

// round 15
// speedup vs baseline: 1.0697x; 1.0683x over previous
#include <cuda_runtime.h>
#include <cuda_fp16.h>
#include <math.h>
#include <stdint.h>

// ---------------- problem constants ----------------
#define NN 20000
#define EE 200000
#define HSZ (1u<<19)
#define HMASK (HSZ-1u)
#define NEG_ORD (-2139095041)

// ---------------- scratch ----------------
__device__ float    g_Qn[NN*256];
__device__ float    g_Vn[NN*256];
__device__ float    g_Ke[EE*256];
__device__ int      g_aggI[NN*256];
__device__ float    g_agg[NN*256];
__device__ float    g_upn[NN*256];
__device__ float    g_osum[NN*256];
__device__ float    g_isum[NN*256];
__device__ int      g_ocnt[NN];
__device__ int      g_icnt[NN];
__device__ int      g_rev[EE];
__device__ unsigned g_hkey[HSZ];
__device__ int      g_hval[HSZ];
// half (fp16) buffers
__device__ __half   g_upe[EE*256];
__device__ __half   g_EB[EE*768];
__device__ __half   g_EC[EE*768];
__device__ __half   g_Xa[NN*768];
__device__ __half   g_Xd[NN*768];
__device__ __half   g_xr[NN*256];
__device__ __half   g_ear[EE*256];
__device__ __half   g_hbuf[EE*768];
__device__ __half   g_cat[NN*512];
__device__ __half   g_hn[NN*512];
__device__ __half   g_twin[NN*512];
__device__ __half   g_We1h[768*1024];
__device__ __half   g_We2h[256*768];
__device__ __half   g_Wqh[256*256];
__device__ __half   g_Wkh[256*256];
__device__ __half   g_Wvh[256*256];
__device__ __half   g_Wn1h[512*512];
__device__ __half   g_Wn2h[256*512];
__device__ __half   g_Weah[256*512];

__device__ __forceinline__ int f2oi(float f){
    int i = __float_as_int(f);
    return i >= 0 ? i : i ^ 0x7FFFFFFF;
}
__device__ __forceinline__ float oi2f(int i){
    return __int_as_float(i >= 0 ? i : i ^ 0x7FFFFFFF);
}

// ---------------- init ----------------
__global__ void k_init(int N){
    int i = blockIdx.x*blockDim.x + threadIdx.x;
    if(i < (int)HSZ) g_hkey[i] = 0xFFFFFFFFu;
    if(i < N*256){ g_aggI[i] = NEG_ORD; g_osum[i] = 0.f; g_isum[i] = 0.f; }
    if(i < N){ g_ocnt[i] = 0; g_icnt[i] = 0; }
}

// ---------------- fp32 -> fp16 convert pass ----------------
__global__ void k_tohalf(const float4* __restrict__ src, uint2* __restrict__ dst, int n4){
    int i = blockIdx.x*blockDim.x + threadIdx.x;
    if(i >= n4) return;
    float4 v = src[i];
    __half2 h0 = __floats2half2_rn(v.x, v.y);
    __half2 h1 = __floats2half2_rn(v.z, v.w);
    dst[i] = make_uint2(*(unsigned*)&h0, *(unsigned*)&h1);
}

// ---------------- reverse-edge hash table (+ degree counts) ----------------
__global__ void k_hash_insert(const int* __restrict__ ei, int E, int N){
    int e = blockIdx.x*blockDim.x + threadIdx.x;
    if(e >= E) return;
    unsigned key = (unsigned)ei[e] * (unsigned)N + (unsigned)ei[E+e];
    unsigned slot = ((key * 2654435761u) >> 13) & HMASK;
    while(true){
        unsigned prev = atomicCAS(&g_hkey[slot], 0xFFFFFFFFu, key);
        if(prev == 0xFFFFFFFFu){ g_hval[slot] = e; break; }
        slot = (slot + 1u) & HMASK;
    }
}

__global__ void k_rev(const int* __restrict__ ei, int E, int N){
    int e = blockIdx.x*blockDim.x + threadIdx.x;
    if(e >= E) return;
    int rr = ei[e], cc = ei[E+e];
    atomicAdd(&g_ocnt[rr], 1);
    atomicAdd(&g_icnt[cc], 1);
    unsigned rkey = (unsigned)cc * (unsigned)N + (unsigned)rr;
    unsigned slot = ((rkey * 2654435761u) >> 13) & HMASK;
    int r = -1;
    while(true){
        unsigned kk = g_hkey[slot];
        if(kk == rkey){ r = g_hval[slot]; break; }
        if(kk == 0xFFFFFFFFu) break;
        slot = (slot + 1u) & HMASK;
    }
    g_rev[e] = r;
}

// ---- fp16 TC GEMM: 128x128 block, warp tile 64x32, cp.async 4-stage ------
#define RSH 40
#define TWB (128*RSH*2)
#define STAGES 4
#define SMEM_BYTES (STAGES*2*TWB)

__device__ __forceinline__ void mma_f16(float c[4], const unsigned a[4], const unsigned b[2]){
    asm volatile(
        "mma.sync.aligned.m16n8k16.row.col.f32.f16.f16.f32 "
        "{%0,%1,%2,%3}, {%4,%5,%6,%7}, {%8,%9}, {%0,%1,%2,%3};"
        : "+f"(c[0]), "+f"(c[1]), "+f"(c[2]), "+f"(c[3])
        : "r"(a[0]), "r"(a[1]), "r"(a[2]), "r"(a[3]), "r"(b[0]), "r"(b[1]));
}
__device__ __forceinline__ void ldsm4(unsigned &r0, unsigned &r1, unsigned &r2, unsigned &r3,
                                      unsigned addr){
    asm volatile("ldmatrix.sync.aligned.m8n8.x4.shared.b16 {%0,%1,%2,%3}, [%4];"
        : "=r"(r0), "=r"(r1), "=r"(r2), "=r"(r3) : "r"(addr));
}
__device__ __forceinline__ void cp16(unsigned daddr, const void* gptr, int srcsize){
    asm volatile("cp.async.cg.shared.global [%0], [%1], 16, %2;"
        :: "r"(daddr), "l"(gptr), "r"(srcsize));
}
__device__ __forceinline__ void cp_commit(){
    asm volatile("cp.async.commit_group;" ::: "memory");
}
__device__ __forceinline__ void cp_wait2(){
    asm volatile("cp.async.wait_group 2;" ::: "memory");
}

// paired emit, one vector store per pair:
// 0: C=v(float2) ; 1: Ch=half2(relu) ; 2: C=v & C2=relu ; 3: C=relu(aux)*sigmoid(v) ;
// 4: Ch=half2(v) ; 5: Ch=half2(v) & C=float2(relu(v))
__device__ __forceinline__ void emit2(float v0, float v1, size_t idx,
                                      float* C, float* C2, __half* Ch,
                                      const float* aux, int mode){
    if(mode == 0){
        *(float2*)(C + idx) = make_float2(v0, v1);
    } else if(mode == 1){
        *(__half2*)(Ch + idx) = __floats2half2_rn(fmaxf(v0,0.f), fmaxf(v1,0.f));
    } else if(mode == 2){
        *(float2*)(C  + idx) = make_float2(v0, v1);
        *(float2*)(C2 + idx) = make_float2(fmaxf(v0,0.f), fmaxf(v1,0.f));
    } else if(mode == 3){
        float2 a = *(const float2*)(aux + idx);
        float s0 = 1.f/(1.f + __expf(-v0));
        float s1 = 1.f/(1.f + __expf(-v1));
        *(float2*)(C + idx) = make_float2(fmaxf(a.x,0.f)*s0, fmaxf(a.y,0.f)*s1);
    } else if(mode == 4){
        *(__half2*)(Ch + idx) = __floats2half2_rn(v0, v1);
    } else {
        *(__half2*)(Ch + idx) = __floats2half2_rn(v0, v1);
        *(float2*)(C + idx)   = make_float2(fmaxf(v0,0.f), fmaxf(v1,0.f));
    }
}

__global__ void __launch_bounds__(256, 2)
k_hgemm(int M, int Ncol, int K,
        const __half* __restrict__ A, int lda,
        const __half* __restrict__ W, int ldw,
        const float* __restrict__ bias,
        float* __restrict__ C, int ldc,
        float* __restrict__ C2, __half* __restrict__ Ch,
        const float* __restrict__ aux, int mode)
{
    extern __shared__ unsigned char smem_raw[];

    const int tid  = threadIdx.x;
    const int lane = tid & 31;
    const int warp = tid >> 5;
    const int tg   = lane & 3;
    const int g    = lane >> 2;
    const int bm   = blockIdx.y * 128;
    const int bn   = blockIdx.x * 128;
    const int mw   = (warp >> 2) * 64;
    const int nw   = (warp & 3) * 32;

    const unsigned sAaddr = (unsigned)__cvta_generic_to_shared(smem_raw);
    const unsigned sBaddr = sAaddr + STAGES*TWB;

    int cR[2], cK8[2];
    #pragma unroll
    for(int i=0;i<2;i++){
        int u = i*256 + tid;
        cR[i] = u >> 2; cK8[i] = (u & 3) << 3;
    }

    auto issue = [&](int kc, int buf){
        const int k0 = kc * 32;
        #pragma unroll
        for(int i=0;i<2;i++){
            unsigned doff = (unsigned)(buf*TWB + cR[i]*(RSH*2) + cK8[i]*2);
            int gm = bm + cR[i];
            const __half* srcA = A + (size_t)(gm < M ? gm : 0)*lda + k0 + cK8[i];
            cp16(sAaddr + doff, srcA, gm < M ? 16 : 0);
            const __half* srcB = W + (size_t)(bn + cR[i])*ldw + k0 + cK8[i];
            cp16(sBaddr + doff, srcB, 16);
        }
        cp_commit();
    };

    const int lr  = lane & 15;
    const int lc8 = (lane >> 4) << 3;
    unsigned aOff[4], bOff[2];
    #pragma unroll
    for(int mi=0;mi<4;mi++)  aOff[mi]  = (unsigned)(((mw + mi*16 + lr)*RSH + lc8) * 2);
    #pragma unroll
    for(int ni2=0;ni2<2;ni2++) bOff[ni2] = (unsigned)(((nw + ni2*16 + lr)*RSH + lc8) * 2);

    float acc[4][4][4];
    #pragma unroll
    for(int mi=0;mi<4;mi++)
        #pragma unroll
        for(int ni=0;ni<4;ni++)
            #pragma unroll
            for(int t=0;t<4;t++) acc[mi][ni][t] = 0.f;

    const int NC = K / 32;
    issue(0, 0); issue(1, 1); issue(2, 2);

    int buf = 0;
    for(int c=0; c<NC; c++){
        cp_wait2();
        __syncthreads();

        if (c + 3 < NC) issue(c + 3, (buf + 3) & 3);
        else            cp_commit();

        const unsigned aBase = sAaddr + (unsigned)(buf*TWB);
        const unsigned bBase = sBaddr + (unsigned)(buf*TWB);
        #pragma unroll
        for(int ks=0;ks<32;ks+=16){
            unsigned af[4][4], bf[4][2];
            #pragma unroll
            for(int mi=0;mi<4;mi++)
                ldsm4(af[mi][0], af[mi][1], af[mi][2], af[mi][3],
                      aBase + aOff[mi] + (unsigned)(ks*2));
            #pragma unroll
            for(int ni2=0;ni2<2;ni2++){
                unsigned r0,r1,r2,r3;
                ldsm4(r0, r1, r2, r3, bBase + bOff[ni2] + (unsigned)(ks*2));
                bf[ni2*2+0][0] = r0; bf[ni2*2+0][1] = r2;
                bf[ni2*2+1][0] = r1; bf[ni2*2+1][1] = r3;
            }
            #pragma unroll
            for(int mi=0;mi<4;mi++)
                #pragma unroll
                for(int ni=0;ni<4;ni++)
                    mma_f16(acc[mi][ni], af[mi], bf[ni]);
        }
        buf = (buf + 1) & 3;
    }

    // ---- epilogue (paired vector stores)
    #pragma unroll
    for(int mi=0;mi<4;mi++){
        int row0 = bm + mw + mi*16 + g;
        int row1 = row0 + 8;
        #pragma unroll
        for(int ni=0;ni<4;ni++){
            int col = bn + nw + ni*8 + tg*2;
            float b0 = bias ? bias[col]   : 0.f;
            float b1 = bias ? bias[col+1] : 0.f;
            if(row0 < M)
                emit2(acc[mi][ni][0] + b0, acc[mi][ni][1] + b1,
                      (size_t)row0*ldc + col, C, C2, Ch, aux, mode);
            if(row1 < M)
                emit2(acc[mi][ni][2] + b0, acc[mi][ni][3] + b1,
                      (size_t)row1*ldc + col, C, C2, Ch, aux, mode);
        }
    }
}

// ---------------- combine (all-fp16 buffers): h = relu(Xa[row]+EB+EC[rev]+Xd[col]+be1)
__global__ void k_combine(const int* __restrict__ ei,
                          const float* __restrict__ be1, int E){
    long long gid = (long long)blockIdx.x*blockDim.x + threadIdx.x;
    if(gid >= (long long)E*192) return;
    int e = (int)(gid/192);
    int q = (int)(gid%192);
    int j = q*4;
    int r  = ei[e], c = ei[E+e], rv = g_rev[e];

    uint2 uv  = *(const uint2*)(g_EB + (size_t)e*768 + j);
    uint2 uxa = *(const uint2*)(g_Xa + (size_t)r*768 + j);
    uint2 uxd = *(const uint2*)(g_Xd + (size_t)c*768 + j);
    float4 b  = *(const float4*)(be1 + j);

    float2 v0  = __half22float2(*(__half2*)&uv.x);
    float2 v1  = __half22float2(*(__half2*)&uv.y);
    float2 xa0 = __half22float2(*(__half2*)&uxa.x);
    float2 xa1 = __half22float2(*(__half2*)&uxa.y);
    float2 xd0 = __half22float2(*(__half2*)&uxd.x);
    float2 xd1 = __half22float2(*(__half2*)&uxd.y);

    float o0 = v0.x + xa0.x + xd0.x + b.x;
    float o1 = v0.y + xa0.y + xd0.y + b.y;
    float o2 = v1.x + xa1.x + xd1.x + b.z;
    float o3 = v1.y + xa1.y + xd1.y + b.w;
    if(rv >= 0){
        uint2 uec = *(const uint2*)(g_EC + (size_t)rv*768 + j);
        float2 e0 = __half22float2(*(__half2*)&uec.x);
        float2 e1 = __half22float2(*(__half2*)&uec.y);
        o0 += e0.x; o1 += e0.y; o2 += e1.x; o3 += e1.y;
    }
    __half2 h0 = __floats2half2_rn(fmaxf(o0,0.f), fmaxf(o1,0.f));
    __half2 h1 = __floats2half2_rn(fmaxf(o2,0.f), fmaxf(o3,0.f));
    *(uint2*)(g_hbuf + (size_t)e*768 + j) = make_uint2(*(unsigned*)&h0, *(unsigned*)&h1);
}

// ---------------- fused attention MLP + softmax + weighted + scatter-max
// (scalar FFMA version — the one measured inside the 2884us R12 run)
__global__ void __launch_bounds__(256)
k_attn(const int* __restrict__ ei,
       const float* __restrict__ Wa1, const float* __restrict__ ba1,
       const float* __restrict__ Wa2, const float* __restrict__ ba2,
       float* __restrict__ out_prob, int E)
{
    __shared__ float4 sW1[1024];
    __shared__ float4 sW2[512];
    __shared__ float  sb1[64], sb2[32];
    for(int i=threadIdx.x;i<1024;i+=256) sW1[i] = ((const float4*)Wa1)[i];
    for(int i=threadIdx.x;i<512; i+=256) sW2[i] = ((const float4*)Wa2)[i];
    if(threadIdx.x < 64) sb1[threadIdx.x] = ba1[threadIdx.x];
    if(threadIdx.x < 32) sb2[threadIdx.x] = ba2[threadIdx.x];
    __syncthreads();

    long long gid = (long long)blockIdx.x*256 + threadIdx.x;
    if(gid >= (long long)E*8) return;
    int e = (int)(gid >> 3);
    int h = (int)(gid & 7);
    int r = ei[e], c = ei[E+e];

    float ain[64];
    const float* qrow = g_Qn + (size_t)r*256 + h;
    const float* krow = g_Ke + (size_t)e*256 + h;
    #pragma unroll
    for(int i=0;i<32;i++) ain[i]    = qrow[i*8];
    #pragma unroll
    for(int i=0;i<32;i++) ain[32+i] = krow[i*8];

    float att[32];
    #pragma unroll
    for(int p=0;p<32;p++) att[p] = sb2[p];

    #pragma unroll 1
    for(int o4=0;o4<16;o4++){
        float a1v[4];
        #pragma unroll
        for(int s=0;s<4;s++){
            int o = o4*4 + s;
            float a = sb1[o];
            #pragma unroll
            for(int c4=0;c4<16;c4++){
                float4 w = sW1[o*16 + c4];
                a += w.x*ain[c4*4+0] + w.y*ain[c4*4+1]
                   + w.z*ain[c4*4+2] + w.w*ain[c4*4+3];
            }
            a1v[s] = fmaxf(a, 0.f);
        }
        #pragma unroll
        for(int p=0;p<32;p++){
            float4 w = sW2[p*16 + o4];
            att[p] += w.x*a1v[0] + w.y*a1v[1] + w.z*a1v[2] + w.w*a1v[3];
        }
    }

    const float invT = 0.17677669529663687f;
    float mx = att[0];
    #pragma unroll
    for(int p=1;p<32;p++) mx = fmaxf(mx, att[p]);
    float sum = 0.f;
    #pragma unroll
    for(int p=0;p<32;p++){ att[p] = __expf((att[p]-mx)*invT); sum += att[p]; }
    float inv = 1.f/sum;

    float* pp = out_prob + (size_t)e*256 + h;
    const float* vrow = g_Vn + (size_t)c*256 + h;
    int* ar = g_aggI + r*256 + h;
    #pragma unroll
    for(int p=0;p<32;p++){
        float pr = att[p]*inv;
        pp[p*8] = pr;
        float w = pr * vrow[p*8];
        atomicMax(ar + p*8, f2oi(w));
    }
}

// ---------------- small elementwise kernels ----------------
__global__ void k_agg_final(int N){
    int i = blockIdx.x*blockDim.x + threadIdx.x;
    if(i >= N*256) return;
    float v = oi2f(g_aggI[i]);
    g_agg[i] = isfinite(v) ? v : 0.f;
}

__global__ void k_concat(const float* __restrict__ x, int N){
    int i = blockIdx.x*blockDim.x + threadIdx.x;
    if(i >= N*512) return;
    int n = i >> 9, j = i & 511;
    float v = (j < 256) ? x[(size_t)n*256 + j] : g_agg[(size_t)n*256 + j - 256];
    g_cat[i] = __float2half_rn(v);
}

__global__ void k_twin_scatter(const int* __restrict__ ei, int E){
    long long gid = (long long)blockIdx.x*blockDim.x + threadIdx.x;
    if(gid >= (long long)E*64) return;
    int e  = (int)(gid >> 6);
    int j4 = (int)(gid & 63);
    int r = ei[e], c = ei[E+e];
    uint2 uu = *(const uint2*)(g_upe + (size_t)e*256 + j4*4);
    float2 u0 = __half22float2(*(__half2*)&uu.x);
    float2 u1 = __half22float2(*(__half2*)&uu.y);
    int base = j4*4;
    atomicAdd(&g_osum[r*256+base+0], u0.x);
    atomicAdd(&g_osum[r*256+base+1], u0.y);
    atomicAdd(&g_osum[r*256+base+2], u1.x);
    atomicAdd(&g_osum[r*256+base+3], u1.y);
    atomicAdd(&g_isum[c*256+base+0], u0.x);
    atomicAdd(&g_isum[c*256+base+1], u0.y);
    atomicAdd(&g_isum[c*256+base+2], u1.x);
    atomicAdd(&g_isum[c*256+base+3], u1.y);
}

__global__ void k_twin_final(int N){
    int i = blockIdx.x*blockDim.x + threadIdx.x;
    if(i >= N*512) return;
    int n = i >> 9, j = i & 511;
    float v;
    if(j < 256) v = g_osum[n*256 + j]       / fmaxf((float)g_ocnt[n], 1.f);
    else        v = g_isum[n*256 + j - 256] / fmaxf((float)g_icnt[n], 1.f);
    g_twin[i] = __float2half_rn(v);
}

// ---------------- launcher ----------------
extern "C" void kernel_launch(void* const* d_in, const int* in_sizes, int n_in,
                              void* d_out, int out_size)
{
    const float* x   = (const float*)d_in[0];
    const float* ea  = (const float*)d_in[1];
    const float* Wq  = (const float*)d_in[2];
    const float* bq  = (const float*)d_in[3];
    const float* Wk  = (const float*)d_in[4];
    const float* bk  = (const float*)d_in[5];
    const float* Wv  = (const float*)d_in[6];
    const float* bv  = (const float*)d_in[7];
    const float* We1 = (const float*)d_in[8];
    const float* be1 = (const float*)d_in[9];
    const float* We2 = (const float*)d_in[10];
    const float* be2 = (const float*)d_in[11];
    const float* Wea = (const float*)d_in[12];
    const float* bea = (const float*)d_in[13];
    const float* Wn1 = (const float*)d_in[14];
    const float* bn1 = (const float*)d_in[15];
    const float* Wn2 = (const float*)d_in[16];
    const float* bn2 = (const float*)d_in[17];
    const float* Wa1 = (const float*)d_in[18];
    const float* ba1 = (const float*)d_in[19];
    const float* Wa2 = (const float*)d_in[20];
    const float* ba2 = (const float*)d_in[21];
    const int*   ei  = (const int*)  d_in[22];

    const int N = in_sizes[0]/256;
    const int E = in_sizes[1]/256;

    float* out      = (float*)d_out;
    float* out_node = out;
    float* out_edge = out + (size_t)N*256;
    float* out_prob = out_edge + (size_t)E*256;

    void* p;
    #define GSYMF(v, s) float* v; cudaGetSymbolAddress(&p, s); v = (float*)p;
    #define GSYMH(v, s) __half* v; cudaGetSymbolAddress(&p, s); v = (__half*)p;
    GSYMF(pQ,   g_Qn)  GSYMF(pV,   g_Vn)  GSYMF(pK,  g_Ke)
    GSYMF(pUpn, g_upn)
    GSYMH(pUPE, g_upe)
    GSYMH(pXa,  g_Xa)  GSYMH(pXd,  g_Xd)  GSYMH(pEB, g_EB) GSYMH(pEC, g_EC)
    GSYMH(pH,   g_hbuf)
    GSYMH(pCat, g_cat) GSYMH(pHn, g_hn)  GSYMH(pTwin, g_twin)
    GSYMH(pXr,  g_xr)  GSYMH(pEar, g_ear)
    GSYMH(pWe1h, g_We1h) GSYMH(pWe2h, g_We2h)
    GSYMH(pWqh, g_Wqh) GSYMH(pWkh, g_Wkh) GSYMH(pWvh, g_Wvh)
    GSYMH(pWn1h, g_Wn1h) GSYMH(pWn2h, g_Wn2h) GSYMH(pWeah, g_Weah)
    #undef GSYMF
    #undef GSYMH

    cudaFuncSetAttribute(k_hgemm, cudaFuncAttributeMaxDynamicSharedMemorySize, SMEM_BYTES);

    auto H = [&](const float* src, __half* dst, int n){
        k_tohalf<<<(n/4 + 255)/256, 256>>>((const float4*)src, (uint2*)dst, n/4);
    };
    H(x,   pXr,   N*256);
    H(ea,  pEar,  E*256);
    H(We1, pWe1h, 768*1024);
    H(We2, pWe2h, 256*768);
    H(Wq,  pWqh,  256*256);
    H(Wk,  pWkh,  256*256);
    H(Wv,  pWvh,  256*256);
    H(Wn1, pWn1h, 512*512);
    H(Wn2, pWn2h, 256*512);
    H(Wea, pWeah, 256*512);

    k_init<<<(NN*256+255)/256, 256>>>(N);
    k_hash_insert<<<(E+255)/256, 256>>>(ei, E, N);
    k_rev<<<(E+255)/256, 256>>>(ei, E, N);

    auto GEMM = [&](int M, int Nc, int K, const __half* A, int lda,
                    const __half* W, int ldw, const float* bias,
                    float* C, int ldc, float* C2, __half* Ch,
                    const float* aux, int mode){
        dim3 g(Nc/128, (M+127)/128);
        k_hgemm<<<g, 256, SMEM_BYTES>>>(M, Nc, K, A, lda, W, ldw, bias,
                                        C, ldc, C2, Ch, aux, mode);
    };

    // edge-update MLP, factored by We1 column blocks (half outputs)
    GEMM(N, 768, 256, pXr,  256, pWe1h + 0,   1024, nullptr, nullptr, 768, nullptr, pXa, nullptr, 4);
    GEMM(N, 768, 256, pXr,  256, pWe1h + 768, 1024, nullptr, nullptr, 768, nullptr, pXd, nullptr, 4);
    GEMM(E, 768, 256, pEar, 256, pWe1h + 256, 1024, nullptr, nullptr, 768, nullptr, pEB, nullptr, 4);
    GEMM(E, 768, 256, pEar, 256, pWe1h + 512, 1024, nullptr, nullptr, 768, nullptr, pEC, nullptr, 4);
    k_combine<<<(int)(((long long)E*192 + 255)/256), 256>>>(ei, be1, E);
    // mode 5: upe half + out_edge relu fp32
    GEMM(E, 256, 768, pH, 768, pWe2h, 768, be2, out_edge, 256, nullptr, pUPE, nullptr, 5);

    // q/v per node, k per edge
    GEMM(N, 256, 256, pXr,  256, pWqh, 256, bq, pQ, 256, nullptr, nullptr, nullptr, 0);
    GEMM(N, 256, 256, pXr,  256, pWvh, 256, bv, pV, 256, nullptr, nullptr, nullptr, 0);
    GEMM(E, 256, 256, pEar, 256, pWkh, 256, bk, pK, 256, nullptr, nullptr, nullptr, 0);

    // attention + scatter-max aggregation
    k_attn<<<(int)(((long long)E*8 + 255)/256), 256>>>(ei, Wa1, ba1, Wa2, ba2, out_prob, E);
    k_agg_final<<<(NN*256+255)/256, 256>>>(N);

    // node update MLP
    k_concat<<<(NN*512+255)/256, 256>>>(x, N);
    GEMM(N, 512, 512, pCat, 512, pWn1h, 512, bn1, nullptr, 512, nullptr, pHn, nullptr, 1);
    GEMM(N, 256, 512, pHn,  512, pWn2h, 512, bn2, pUpn, 256, nullptr, nullptr, nullptr, 0);

    // twin aggregation + gated output
    k_twin_scatter<<<(int)(((long long)E*64 + 255)/256), 256>>>(ei, E);
    k_twin_final<<<(NN*512+255)/256, 256>>>(N);
    GEMM(N, 256, 512, pTwin, 512, pWeah, 512, bea, out_node, 256, nullptr, nullptr, pUpn, 3);
}

// round 16
// speedup vs baseline: 1.0819x; 1.0114x over previous
#include <cuda_runtime.h>
#include <cuda_fp16.h>
#include <math.h>
#include <stdint.h>

// ---------------- problem constants ----------------
#define NN 20000
#define EE 200000
#define HSZ (1u<<19)
#define HMASK (HSZ-1u)
#define NEG_ORD (-2139095041)

// ---------------- scratch ----------------
__device__ float    g_Qn[NN*256];
__device__ float    g_Vn[NN*256];
__device__ float    g_Ke[EE*256];
__device__ int      g_aggI[NN*256];
__device__ float    g_upn[NN*256];
__device__ float    g_osum[NN*256];
__device__ float    g_isum[NN*256];
__device__ int      g_ocnt[NN];
__device__ int      g_icnt[NN];
__device__ int      g_rev[EE];
__device__ unsigned g_hkey[HSZ];
__device__ int      g_hval[HSZ];
// half (fp16) buffers
__device__ __half   g_upe[EE*256];
__device__ __half   g_EC[EE*768];
__device__ __half   g_Xa[NN*768];
__device__ __half   g_Xd[NN*768];
__device__ __half   g_xr[NN*256];
__device__ __half   g_ear[EE*256];
__device__ __half   g_hbuf[EE*768];
__device__ __half   g_cat[NN*512];
__device__ __half   g_hn[NN*512];
__device__ __half   g_twin[NN*512];
__device__ __half   g_We1h[768*1024];
__device__ __half   g_We2h[256*768];
__device__ __half   g_Wqh[256*256];
__device__ __half   g_Wkh[256*256];
__device__ __half   g_Wvh[256*256];
__device__ __half   g_Wn1h[512*512];
__device__ __half   g_Wn2h[256*512];
__device__ __half   g_Weah[256*512];

__device__ __forceinline__ int f2oi(float f){
    int i = __float_as_int(f);
    return i >= 0 ? i : i ^ 0x7FFFFFFF;
}
__device__ __forceinline__ float oi2f(int i){
    return __int_as_float(i >= 0 ? i : i ^ 0x7FFFFFFF);
}

// ---------------- init ----------------
__global__ void k_init(int N){
    int i = blockIdx.x*blockDim.x + threadIdx.x;
    if(i < (int)HSZ) g_hkey[i] = 0xFFFFFFFFu;
    if(i < N*256){ g_aggI[i] = NEG_ORD; g_osum[i] = 0.f; g_isum[i] = 0.f; }
    if(i < N){ g_ocnt[i] = 0; g_icnt[i] = 0; }
}

// ---------------- fp32 -> fp16 convert pass ----------------
__global__ void k_tohalf(const float4* __restrict__ src, uint2* __restrict__ dst, int n4){
    int i = blockIdx.x*blockDim.x + threadIdx.x;
    if(i >= n4) return;
    float4 v = src[i];
    __half2 h0 = __floats2half2_rn(v.x, v.y);
    __half2 h1 = __floats2half2_rn(v.z, v.w);
    dst[i] = make_uint2(*(unsigned*)&h0, *(unsigned*)&h1);
}

// ---------------- reverse-edge hash table (+ degree counts) ----------------
__global__ void k_hash_insert(const int* __restrict__ ei, int E, int N){
    int e = blockIdx.x*blockDim.x + threadIdx.x;
    if(e >= E) return;
    unsigned key = (unsigned)ei[e] * (unsigned)N + (unsigned)ei[E+e];
    unsigned slot = ((key * 2654435761u) >> 13) & HMASK;
    while(true){
        unsigned prev = atomicCAS(&g_hkey[slot], 0xFFFFFFFFu, key);
        if(prev == 0xFFFFFFFFu){ g_hval[slot] = e; break; }
        slot = (slot + 1u) & HMASK;
    }
}

__global__ void k_rev(const int* __restrict__ ei, int E, int N){
    int e = blockIdx.x*blockDim.x + threadIdx.x;
    if(e >= E) return;
    int rr = ei[e], cc = ei[E+e];
    atomicAdd(&g_ocnt[rr], 1);
    atomicAdd(&g_icnt[cc], 1);
    unsigned rkey = (unsigned)cc * (unsigned)N + (unsigned)rr;
    unsigned slot = ((rkey * 2654435761u) >> 13) & HMASK;
    int r = -1;
    while(true){
        unsigned kk = g_hkey[slot];
        if(kk == rkey){ r = g_hval[slot]; break; }
        if(kk == 0xFFFFFFFFu) break;
        slot = (slot + 1u) & HMASK;
    }
    g_rev[e] = r;
}

// ---- fp16 TC GEMM: 128x128 block, warp tile 64x32, cp.async 4-stage ------
#define RSH 40
#define TWB (128*RSH*2)
#define STAGES 4
#define SMEM_BYTES (STAGES*2*TWB)

__device__ __forceinline__ void mma_f16(float c[4], const unsigned a[4], const unsigned b[2]){
    asm volatile(
        "mma.sync.aligned.m16n8k16.row.col.f32.f16.f16.f32 "
        "{%0,%1,%2,%3}, {%4,%5,%6,%7}, {%8,%9}, {%0,%1,%2,%3};"
        : "+f"(c[0]), "+f"(c[1]), "+f"(c[2]), "+f"(c[3])
        : "r"(a[0]), "r"(a[1]), "r"(a[2]), "r"(a[3]), "r"(b[0]), "r"(b[1]));
}
__device__ __forceinline__ void ldsm4(unsigned &r0, unsigned &r1, unsigned &r2, unsigned &r3,
                                      unsigned addr){
    asm volatile("ldmatrix.sync.aligned.m8n8.x4.shared.b16 {%0,%1,%2,%3}, [%4];"
        : "=r"(r0), "=r"(r1), "=r"(r2), "=r"(r3) : "r"(addr));
}
__device__ __forceinline__ void cp16(unsigned daddr, const void* gptr, int srcsize){
    asm volatile("cp.async.cg.shared.global [%0], [%1], 16, %2;"
        :: "r"(daddr), "l"(gptr), "r"(srcsize));
}
__device__ __forceinline__ void cp_commit(){
    asm volatile("cp.async.commit_group;" ::: "memory");
}
__device__ __forceinline__ void cp_wait2(){
    asm volatile("cp.async.wait_group 2;" ::: "memory");
}

// paired emit, one vector store per pair:
// 0: C=v(float2) ; 1: Ch=half2(relu) ; 2: C=v & C2=relu ; 3: C=relu(aux)*sigmoid(v) ;
// 4: Ch=half2(v) ; 5: Ch=half2(v) & C=float2(relu(v))
__device__ __forceinline__ void emit2(float v0, float v1, size_t idx,
                                      float* C, float* C2, __half* Ch,
                                      const float* aux, int mode){
    if(mode == 0){
        *(float2*)(C + idx) = make_float2(v0, v1);
    } else if(mode == 1){
        *(__half2*)(Ch + idx) = __floats2half2_rn(fmaxf(v0,0.f), fmaxf(v1,0.f));
    } else if(mode == 2){
        *(float2*)(C  + idx) = make_float2(v0, v1);
        *(float2*)(C2 + idx) = make_float2(fmaxf(v0,0.f), fmaxf(v1,0.f));
    } else if(mode == 3){
        float2 a = *(const float2*)(aux + idx);
        float s0 = 1.f/(1.f + __expf(-v0));
        float s1 = 1.f/(1.f + __expf(-v1));
        *(float2*)(C + idx) = make_float2(fmaxf(a.x,0.f)*s0, fmaxf(a.y,0.f)*s1);
    } else if(mode == 4){
        *(__half2*)(Ch + idx) = __floats2half2_rn(v0, v1);
    } else {
        *(__half2*)(Ch + idx) = __floats2half2_rn(v0, v1);
        *(float2*)(C + idx)   = make_float2(fmaxf(v0,0.f), fmaxf(v1,0.f));
    }
}

// mode 6: fused combine epilogue — Ch[row,col] = half(relu(acc + bias[col]
//         + Xa[ei[row],col] + Xd[ei[M+row],col] + EC[rev[row],col]))
__global__ void __launch_bounds__(256, 2)
k_hgemm(int M, int Ncol, int K,
        const __half* __restrict__ A, int lda,
        const __half* __restrict__ W, int ldw,
        const float* __restrict__ bias,
        float* __restrict__ C, int ldc,
        float* __restrict__ C2, __half* __restrict__ Ch,
        const float* __restrict__ aux, int mode,
        const int* __restrict__ eidx, const int* __restrict__ revp,
        const __half* __restrict__ Xah, const __half* __restrict__ Xdh,
        const __half* __restrict__ ECh)
{
    extern __shared__ unsigned char smem_raw[];

    const int tid  = threadIdx.x;
    const int lane = tid & 31;
    const int warp = tid >> 5;
    const int tg   = lane & 3;
    const int g    = lane >> 2;
    const int bm   = blockIdx.y * 128;
    const int bn   = blockIdx.x * 128;
    const int mw   = (warp >> 2) * 64;
    const int nw   = (warp & 3) * 32;

    const unsigned sAaddr = (unsigned)__cvta_generic_to_shared(smem_raw);
    const unsigned sBaddr = sAaddr + STAGES*TWB;

    int cR[2], cK8[2];
    #pragma unroll
    for(int i=0;i<2;i++){
        int u = i*256 + tid;
        cR[i] = u >> 2; cK8[i] = (u & 3) << 3;
    }

    auto issue = [&](int kc, int buf){
        const int k0 = kc * 32;
        #pragma unroll
        for(int i=0;i<2;i++){
            unsigned doff = (unsigned)(buf*TWB + cR[i]*(RSH*2) + cK8[i]*2);
            int gm = bm + cR[i];
            const __half* srcA = A + (size_t)(gm < M ? gm : 0)*lda + k0 + cK8[i];
            cp16(sAaddr + doff, srcA, gm < M ? 16 : 0);
            const __half* srcB = W + (size_t)(bn + cR[i])*ldw + k0 + cK8[i];
            cp16(sBaddr + doff, srcB, 16);
        }
        cp_commit();
    };

    const int lr  = lane & 15;
    const int lc8 = (lane >> 4) << 3;
    unsigned aOff[4], bOff[2];
    #pragma unroll
    for(int mi=0;mi<4;mi++)  aOff[mi]  = (unsigned)(((mw + mi*16 + lr)*RSH + lc8) * 2);
    #pragma unroll
    for(int ni2=0;ni2<2;ni2++) bOff[ni2] = (unsigned)(((nw + ni2*16 + lr)*RSH + lc8) * 2);

    float acc[4][4][4];
    #pragma unroll
    for(int mi=0;mi<4;mi++)
        #pragma unroll
        for(int ni=0;ni<4;ni++)
            #pragma unroll
            for(int t=0;t<4;t++) acc[mi][ni][t] = 0.f;

    const int NC = K / 32;
    issue(0, 0); issue(1, 1); issue(2, 2);

    int buf = 0;
    for(int c=0; c<NC; c++){
        cp_wait2();
        __syncthreads();

        if (c + 3 < NC) issue(c + 3, (buf + 3) & 3);
        else            cp_commit();

        const unsigned aBase = sAaddr + (unsigned)(buf*TWB);
        const unsigned bBase = sBaddr + (unsigned)(buf*TWB);
        #pragma unroll
        for(int ks=0;ks<32;ks+=16){
            unsigned af[4][4], bf[4][2];
            #pragma unroll
            for(int mi=0;mi<4;mi++)
                ldsm4(af[mi][0], af[mi][1], af[mi][2], af[mi][3],
                      aBase + aOff[mi] + (unsigned)(ks*2));
            #pragma unroll
            for(int ni2=0;ni2<2;ni2++){
                unsigned r0,r1,r2,r3;
                ldsm4(r0, r1, r2, r3, bBase + bOff[ni2] + (unsigned)(ks*2));
                bf[ni2*2+0][0] = r0; bf[ni2*2+0][1] = r2;
                bf[ni2*2+1][0] = r1; bf[ni2*2+1][1] = r3;
            }
            #pragma unroll
            for(int mi=0;mi<4;mi++)
                #pragma unroll
                for(int ni=0;ni<4;ni++)
                    mma_f16(acc[mi][ni], af[mi], bf[ni]);
        }
        buf = (buf + 1) & 3;
    }

    // ---- epilogue
    if(mode == 6){
        #pragma unroll
        for(int mi=0;mi<4;mi++){
            #pragma unroll
            for(int rr2=0;rr2<2;rr2++){
                int row = bm + mw + mi*16 + g + rr2*8;
                if(row >= M) continue;
                int r  = eidx[row];
                int cc = eidx[M + row];
                int rv = revp[row];
                const __half* xaRow = Xah + (size_t)r *768;
                const __half* xdRow = Xdh + (size_t)cc*768;
                const __half* ecRow = (rv >= 0) ? (ECh + (size_t)rv*768) : nullptr;
                #pragma unroll
                for(int ni=0;ni<4;ni++){
                    int col = bn + nw + ni*8 + tg*2;
                    float v0 = acc[mi][ni][rr2*2+0] + bias[col];
                    float v1 = acc[mi][ni][rr2*2+1] + bias[col+1];
                    float2 xa = __half22float2(*(const __half2*)(xaRow + col));
                    float2 xd = __half22float2(*(const __half2*)(xdRow + col));
                    v0 += xa.x + xd.x; v1 += xa.y + xd.y;
                    if(ecRow){
                        float2 ec = __half22float2(*(const __half2*)(ecRow + col));
                        v0 += ec.x; v1 += ec.y;
                    }
                    *(__half2*)(Ch + (size_t)row*ldc + col) =
                        __floats2half2_rn(fmaxf(v0,0.f), fmaxf(v1,0.f));
                }
            }
        }
        return;
    }

    #pragma unroll
    for(int mi=0;mi<4;mi++){
        int row0 = bm + mw + mi*16 + g;
        int row1 = row0 + 8;
        #pragma unroll
        for(int ni=0;ni<4;ni++){
            int col = bn + nw + ni*8 + tg*2;
            float b0 = bias ? bias[col]   : 0.f;
            float b1 = bias ? bias[col+1] : 0.f;
            if(row0 < M)
                emit2(acc[mi][ni][0] + b0, acc[mi][ni][1] + b1,
                      (size_t)row0*ldc + col, C, C2, Ch, aux, mode);
            if(row1 < M)
                emit2(acc[mi][ni][2] + b0, acc[mi][ni][3] + b1,
                      (size_t)row1*ldc + col, C, C2, Ch, aux, mode);
        }
    }
}

// ---------------- fused attention MLP + softmax + weighted + scatter-max
__global__ void __launch_bounds__(256)
k_attn(const int* __restrict__ ei,
       const float* __restrict__ Wa1, const float* __restrict__ ba1,
       const float* __restrict__ Wa2, const float* __restrict__ ba2,
       float* __restrict__ out_prob, int E)
{
    __shared__ float4 sW1[1024];
    __shared__ float4 sW2[512];
    __shared__ float  sb1[64], sb2[32];
    for(int i=threadIdx.x;i<1024;i+=256) sW1[i] = ((const float4*)Wa1)[i];
    for(int i=threadIdx.x;i<512; i+=256) sW2[i] = ((const float4*)Wa2)[i];
    if(threadIdx.x < 64) sb1[threadIdx.x] = ba1[threadIdx.x];
    if(threadIdx.x < 32) sb2[threadIdx.x] = ba2[threadIdx.x];
    __syncthreads();

    long long gid = (long long)blockIdx.x*256 + threadIdx.x;
    if(gid >= (long long)E*8) return;
    int e = (int)(gid >> 3);
    int h = (int)(gid & 7);
    int r = ei[e], c = ei[E+e];

    float ain[64];
    const float* qrow = g_Qn + (size_t)r*256 + h;
    const float* krow = g_Ke + (size_t)e*256 + h;
    #pragma unroll
    for(int i=0;i<32;i++) ain[i]    = qrow[i*8];
    #pragma unroll
    for(int i=0;i<32;i++) ain[32+i] = krow[i*8];

    float att[32];
    #pragma unroll
    for(int p=0;p<32;p++) att[p] = sb2[p];

    #pragma unroll 1
    for(int o4=0;o4<16;o4++){
        float a1v[4];
        #pragma unroll
        for(int s=0;s<4;s++){
            int o = o4*4 + s;
            float a = sb1[o];
            #pragma unroll
            for(int c4=0;c4<16;c4++){
                float4 w = sW1[o*16 + c4];
                a += w.x*ain[c4*4+0] + w.y*ain[c4*4+1]
                   + w.z*ain[c4*4+2] + w.w*ain[c4*4+3];
            }
            a1v[s] = fmaxf(a, 0.f);
        }
        #pragma unroll
        for(int p=0;p<32;p++){
            float4 w = sW2[p*16 + o4];
            att[p] += w.x*a1v[0] + w.y*a1v[1] + w.z*a1v[2] + w.w*a1v[3];
        }
    }

    const float invT = 0.17677669529663687f;
    float mx = att[0];
    #pragma unroll
    for(int p=1;p<32;p++) mx = fmaxf(mx, att[p]);
    float sum = 0.f;
    #pragma unroll
    for(int p=0;p<32;p++){ att[p] = __expf((att[p]-mx)*invT); sum += att[p]; }
    float inv = 1.f/sum;

    float* pp = out_prob + (size_t)e*256 + h;
    const float* vrow = g_Vn + (size_t)c*256 + h;
    int* ar = g_aggI + r*256 + h;
    #pragma unroll
    for(int p=0;p<32;p++){
        float pr = att[p]*inv;
        pp[p*8] = pr;
        float w = pr * vrow[p*8];
        atomicMax(ar + p*8, f2oi(w));
    }
}

// ---------------- small elementwise kernels ----------------
// fused agg finalize + concat into g_cat (half)
__global__ void k_concat(const float* __restrict__ x, int N){
    int i = blockIdx.x*blockDim.x + threadIdx.x;
    if(i >= N*512) return;
    int n = i >> 9, j = i & 511;
    float v;
    if(j < 256){
        v = x[(size_t)n*256 + j];
    } else {
        float a = oi2f(g_aggI[(size_t)n*256 + j - 256]);
        v = isfinite(a) ? a : 0.f;
    }
    g_cat[i] = __float2half_rn(v);
}

__global__ void k_twin_scatter(const int* __restrict__ ei, int E){
    long long gid = (long long)blockIdx.x*blockDim.x + threadIdx.x;
    if(gid >= (long long)E*64) return;
    int e  = (int)(gid >> 6);
    int j4 = (int)(gid & 63);
    int r = ei[e], c = ei[E+e];
    uint2 uu = *(const uint2*)(g_upe + (size_t)e*256 + j4*4);
    float2 u0 = __half22float2(*(__half2*)&uu.x);
    float2 u1 = __half22float2(*(__half2*)&uu.y);
    int base = j4*4;
    atomicAdd(&g_osum[r*256+base+0], u0.x);
    atomicAdd(&g_osum[r*256+base+1], u0.y);
    atomicAdd(&g_osum[r*256+base+2], u1.x);
    atomicAdd(&g_osum[r*256+base+3], u1.y);
    atomicAdd(&g_isum[c*256+base+0], u0.x);
    atomicAdd(&g_isum[c*256+base+1], u0.y);
    atomicAdd(&g_isum[c*256+base+2], u1.x);
    atomicAdd(&g_isum[c*256+base+3], u1.y);
}

__global__ void k_twin_final(int N){
    int i = blockIdx.x*blockDim.x + threadIdx.x;
    if(i >= N*512) return;
    int n = i >> 9, j = i & 511;
    float v;
    if(j < 256) v = g_osum[n*256 + j]       / fmaxf((float)g_ocnt[n], 1.f);
    else        v = g_isum[n*256 + j - 256] / fmaxf((float)g_icnt[n], 1.f);
    g_twin[i] = __float2half_rn(v);
}

// ---------------- launcher ----------------
extern "C" void kernel_launch(void* const* d_in, const int* in_sizes, int n_in,
                              void* d_out, int out_size)
{
    const float* x   = (const float*)d_in[0];
    const float* ea  = (const float*)d_in[1];
    const float* Wq  = (const float*)d_in[2];
    const float* bq  = (const float*)d_in[3];
    const float* Wk  = (const float*)d_in[4];
    const float* bk  = (const float*)d_in[5];
    const float* Wv  = (const float*)d_in[6];
    const float* bv  = (const float*)d_in[7];
    const float* We1 = (const float*)d_in[8];
    const float* be1 = (const float*)d_in[9];
    const float* We2 = (const float*)d_in[10];
    const float* be2 = (const float*)d_in[11];
    const float* Wea = (const float*)d_in[12];
    const float* bea = (const float*)d_in[13];
    const float* Wn1 = (const float*)d_in[14];
    const float* bn1 = (const float*)d_in[15];
    const float* Wn2 = (const float*)d_in[16];
    const float* bn2 = (const float*)d_in[17];
    const float* Wa1 = (const float*)d_in[18];
    const float* ba1 = (const float*)d_in[19];
    const float* Wa2 = (const float*)d_in[20];
    const float* ba2 = (const float*)d_in[21];
    const int*   ei  = (const int*)  d_in[22];

    const int N = in_sizes[0]/256;
    const int E = in_sizes[1]/256;

    float* out      = (float*)d_out;
    float* out_node = out;
    float* out_edge = out + (size_t)N*256;
    float* out_prob = out_edge + (size_t)E*256;

    void* p;
    #define GSYMF(v, s) float* v; cudaGetSymbolAddress(&p, s); v = (float*)p;
    #define GSYMI(v, s) int* v; cudaGetSymbolAddress(&p, s); v = (int*)p;
    #define GSYMH(v, s) __half* v; cudaGetSymbolAddress(&p, s); v = (__half*)p;
    GSYMF(pQ,   g_Qn)  GSYMF(pV,   g_Vn)  GSYMF(pK,  g_Ke)
    GSYMF(pUpn, g_upn)
    GSYMI(pRev, g_rev)
    GSYMH(pUPE, g_upe)
    GSYMH(pXa,  g_Xa)  GSYMH(pXd,  g_Xd)  GSYMH(pEC, g_EC)
    GSYMH(pH,   g_hbuf)
    GSYMH(pCat, g_cat) GSYMH(pHn, g_hn)  GSYMH(pTwin, g_twin)
    GSYMH(pXr,  g_xr)  GSYMH(pEar, g_ear)
    GSYMH(pWe1h, g_We1h) GSYMH(pWe2h, g_We2h)
    GSYMH(pWqh, g_Wqh) GSYMH(pWkh, g_Wkh) GSYMH(pWvh, g_Wvh)
    GSYMH(pWn1h, g_Wn1h) GSYMH(pWn2h, g_Wn2h) GSYMH(pWeah, g_Weah)
    #undef GSYMF
    #undef GSYMI
    #undef GSYMH

    cudaFuncSetAttribute(k_hgemm, cudaFuncAttributeMaxDynamicSharedMemorySize, SMEM_BYTES);

    auto H = [&](const float* src, __half* dst, int n){
        k_tohalf<<<(n/4 + 255)/256, 256>>>((const float4*)src, (uint2*)dst, n/4);
    };
    H(x,   pXr,   N*256);
    H(ea,  pEar,  E*256);
    H(We1, pWe1h, 768*1024);
    H(We2, pWe2h, 256*768);
    H(Wq,  pWqh,  256*256);
    H(Wk,  pWkh,  256*256);
    H(Wv,  pWvh,  256*256);
    H(Wn1, pWn1h, 512*512);
    H(Wn2, pWn2h, 256*512);
    H(Wea, pWeah, 256*512);

    k_init<<<(NN*256+255)/256, 256>>>(N);
    k_hash_insert<<<(E+255)/256, 256>>>(ei, E, N);
    k_rev<<<(E+255)/256, 256>>>(ei, E, N);

    auto GEMM = [&](int M, int Nc, int K, const __half* A, int lda,
                    const __half* W, int ldw, const float* bias,
                    float* C, int ldc, float* C2, __half* Ch,
                    const float* aux, int mode,
                    const int* eidx = nullptr, const int* revp = nullptr,
                    const __half* Xah = nullptr, const __half* Xdh = nullptr,
                    const __half* ECh = nullptr){
        dim3 g(Nc/128, (M+127)/128);
        k_hgemm<<<g, 256, SMEM_BYTES>>>(M, Nc, K, A, lda, W, ldw, bias,
                                        C, ldc, C2, Ch, aux, mode,
                                        eidx, revp, Xah, Xdh, ECh);
    };

    // edge-update MLP, factored by We1 column blocks.
    // Xa, Xd, EC first (half outputs); then EB GEMM with fused combine -> hbuf.
    GEMM(N, 768, 256, pXr,  256, pWe1h + 0,   1024, nullptr, nullptr, 768, nullptr, pXa, nullptr, 4);
    GEMM(N, 768, 256, pXr,  256, pWe1h + 768, 1024, nullptr, nullptr, 768, nullptr, pXd, nullptr, 4);
    GEMM(E, 768, 256, pEar, 256, pWe1h + 512, 1024, nullptr, nullptr, 768, nullptr, pEC, nullptr, 4);
    GEMM(E, 768, 256, pEar, 256, pWe1h + 256, 1024, be1, nullptr, 768, nullptr, pH, nullptr, 6,
         ei, pRev, pXa, pXd, pEC);
    // mode 5: upe half + out_edge relu fp32
    GEMM(E, 256, 768, pH, 768, pWe2h, 768, be2, out_edge, 256, nullptr, pUPE, nullptr, 5);

    // q/v per node, k per edge
    GEMM(N, 256, 256, pXr,  256, pWqh, 256, bq, pQ, 256, nullptr, nullptr, nullptr, 0);
    GEMM(N, 256, 256, pXr,  256, pWvh, 256, bv, pV, 256, nullptr, nullptr, nullptr, 0);
    GEMM(E, 256, 256, pEar, 256, pWkh, 256, bk, pK, 256, nullptr, nullptr, nullptr, 0);

    // attention + scatter-max aggregation
    k_attn<<<(int)(((long long)E*8 + 255)/256), 256>>>(ei, Wa1, ba1, Wa2, ba2, out_prob, E);

    // node update MLP (agg finalize fused into concat)
    k_concat<<<(NN*512+255)/256, 256>>>(x, N);
    GEMM(N, 512, 512, pCat, 512, pWn1h, 512, bn1, nullptr, 512, nullptr, pHn, nullptr, 1);
    GEMM(N, 256, 512, pHn,  512, pWn2h, 512, bn2, pUpn, 256, nullptr, nullptr, nullptr, 0);

    // twin aggregation + gated output
    k_twin_scatter<<<(int)(((long long)E*64 + 255)/256), 256>>>(ei, E);
    k_twin_final<<<(NN*512+255)/256, 256>>>(N);
    GEMM(N, 256, 512, pTwin, 512, pWeah, 512, bea, out_node, 256, nullptr, nullptr, pUpn, 3);
}

// round 17
// speedup vs baseline: 1.1626x; 1.0746x over previous
#include <cuda_runtime.h>
#include <cuda_fp16.h>
#include <math.h>
#include <stdint.h>

// ---------------- problem constants ----------------
#define NN 20000
#define EE 200000
#define HSZ (1u<<19)
#define HMASK (HSZ-1u)
#define NEG_ORD (-2139095041)

// ---------------- scratch ----------------
__device__ float    g_Vn[NN*256];
__device__ int      g_aggI[NN*256];
__device__ float    g_upn[NN*256];
__device__ float    g_osum[NN*256];
__device__ float    g_isum[NN*256];
__device__ int      g_ocnt[NN];
__device__ int      g_icnt[NN];
__device__ int      g_rev[EE];
__device__ unsigned g_hkey[HSZ];
__device__ int      g_hval[HSZ];
__device__ float    g_bqp[256];
__device__ float    g_bkp[256];
__device__ float    g_b1d[128];
// half (fp16) buffers
__device__ __half   g_upe[EE*256];
__device__ __half   g_EC[EE*768];
__device__ __half   g_Xa[NN*768];
__device__ __half   g_Xd[NN*768];
__device__ __half   g_xr[NN*256];
__device__ __half   g_ear[EE*256];
__device__ __half   g_hbuf[EE*768];
__device__ __half   g_cat[NN*512];
__device__ __half   g_hn[NN*512];
__device__ __half   g_twin[NN*512];
__device__ __half   g_Qh[NN*256];     // head-major q (half)
__device__ __half   g_Kh[EE*256];     // head-major k (half)
__device__ __half   g_Qa[NN*512];     // (N*4) x 128: layer-1 q-part + bias
__device__ __half   g_Ka[EE*512];     // (E*4) x 128: layer-1 k-part
__device__ __half   g_W1a[128*64];    // block-diag packed, q-part
__device__ __half   g_W1b[128*64];    // block-diag packed, k-part
__device__ __half   g_We1h[768*1024];
__device__ __half   g_We2h[256*768];
__device__ __half   g_Wqh[256*256];
__device__ __half   g_Wkh[256*256];
__device__ __half   g_Wvh[256*256];
__device__ __half   g_Wn1h[512*512];
__device__ __half   g_Wn2h[256*512];
__device__ __half   g_Weah[256*512];

__device__ __forceinline__ int f2oi(float f){
    int i = __float_as_int(f);
    return i >= 0 ? i : i ^ 0x7FFFFFFF;
}
__device__ __forceinline__ float oi2f(int i){
    return __int_as_float(i >= 0 ? i : i ^ 0x7FFFFFFF);
}

// ---------------- init ----------------
__global__ void k_init(int N){
    int i = blockIdx.x*blockDim.x + threadIdx.x;
    if(i < (int)HSZ) g_hkey[i] = 0xFFFFFFFFu;
    if(i < N*256){ g_aggI[i] = NEG_ORD; g_osum[i] = 0.f; g_isum[i] = 0.f; }
    if(i < N){ g_ocnt[i] = 0; g_icnt[i] = 0; }
}

// ---------------- fp32 -> fp16 convert pass ----------------
__global__ void k_tohalf(const float4* __restrict__ src, uint2* __restrict__ dst, int n4){
    int i = blockIdx.x*blockDim.x + threadIdx.x;
    if(i >= n4) return;
    float4 v = src[i];
    __half2 h0 = __floats2half2_rn(v.x, v.y);
    __half2 h1 = __floats2half2_rn(v.z, v.w);
    dst[i] = make_uint2(*(unsigned*)&h0, *(unsigned*)&h1);
}

// head-major permuted weight convert for Wq/Wk: dst row n = src row (n&31)*8+(n>>5)
__global__ void k_permqk(const float* __restrict__ src, __half* __restrict__ dst){
    int i = blockIdx.x*blockDim.x + threadIdx.x;
    if(i >= 256*64) return;
    int n = i >> 6, k4 = (i & 63) << 2;
    int srow = ((n & 31) << 3) + (n >> 5);
    float4 v = *(const float4*)(src + srow*256 + k4);
    __half2 h0 = __floats2half2_rn(v.x, v.y);
    __half2 h1 = __floats2half2_rn(v.z, v.w);
    *(uint2*)(dst + n*256 + k4) = make_uint2(*(unsigned*)&h0, *(unsigned*)&h1);
}
__global__ void k_permbias(const float* __restrict__ bq, const float* __restrict__ bk){
    int n = threadIdx.x;
    int srow = ((n & 31) << 3) + (n >> 5);
    g_bqp[n] = bq[srow];
    g_bkp[n] = bk[srow];
}

// block-diagonal packed layer-1 weights (two heads per GEMM row) + doubled bias
__global__ void k_prepw1(const float* __restrict__ Wa1, const float* __restrict__ ba1){
    int i = blockIdx.x*blockDim.x + threadIdx.x;
    if(i >= 128*64) return;
    int n = i >> 6, k = i & 63;
    float va = 0.f, vb = 0.f;
    if(n < 64){ if(k < 32){ va = Wa1[n*64 + k]; vb = Wa1[n*64 + 32 + k]; } }
    else      { if(k >= 32){ va = Wa1[(n-64)*64 + (k-32)]; vb = Wa1[(n-64)*64 + 32 + (k-32)]; } }
    g_W1a[i] = __float2half_rn(va);
    g_W1b[i] = __float2half_rn(vb);
    if(i < 128) g_b1d[i] = ba1[i & 63];
}

// ---------------- reverse-edge hash table (+ degree counts) ----------------
__global__ void k_hash_insert(const int* __restrict__ ei, int E, int N){
    int e = blockIdx.x*blockDim.x + threadIdx.x;
    if(e >= E) return;
    unsigned key = (unsigned)ei[e] * (unsigned)N + (unsigned)ei[E+e];
    unsigned slot = ((key * 2654435761u) >> 13) & HMASK;
    while(true){
        unsigned prev = atomicCAS(&g_hkey[slot], 0xFFFFFFFFu, key);
        if(prev == 0xFFFFFFFFu){ g_hval[slot] = e; break; }
        slot = (slot + 1u) & HMASK;
    }
}

__global__ void k_rev(const int* __restrict__ ei, int E, int N){
    int e = blockIdx.x*blockDim.x + threadIdx.x;
    if(e >= E) return;
    int rr = ei[e], cc = ei[E+e];
    atomicAdd(&g_ocnt[rr], 1);
    atomicAdd(&g_icnt[cc], 1);
    unsigned rkey = (unsigned)cc * (unsigned)N + (unsigned)rr;
    unsigned slot = ((rkey * 2654435761u) >> 13) & HMASK;
    int r = -1;
    while(true){
        unsigned kk = g_hkey[slot];
        if(kk == rkey){ r = g_hval[slot]; break; }
        if(kk == 0xFFFFFFFFu) break;
        slot = (slot + 1u) & HMASK;
    }
    g_rev[e] = r;
}

// ---- fp16 TC GEMM: 128x128 block, warp tile 64x32, cp.async 4-stage ------
#define RSH 40
#define TWB (128*RSH*2)
#define STAGES 4
#define SMEM_BYTES (STAGES*2*TWB)

__device__ __forceinline__ void mma_f16(float c[4], const unsigned a[4], const unsigned b[2]){
    asm volatile(
        "mma.sync.aligned.m16n8k16.row.col.f32.f16.f16.f32 "
        "{%0,%1,%2,%3}, {%4,%5,%6,%7}, {%8,%9}, {%0,%1,%2,%3};"
        : "+f"(c[0]), "+f"(c[1]), "+f"(c[2]), "+f"(c[3])
        : "r"(a[0]), "r"(a[1]), "r"(a[2]), "r"(a[3]), "r"(b[0]), "r"(b[1]));
}
__device__ __forceinline__ void ldsm4(unsigned &r0, unsigned &r1, unsigned &r2, unsigned &r3,
                                      unsigned addr){
    asm volatile("ldmatrix.sync.aligned.m8n8.x4.shared.b16 {%0,%1,%2,%3}, [%4];"
        : "=r"(r0), "=r"(r1), "=r"(r2), "=r"(r3) : "r"(addr));
}
__device__ __forceinline__ void cp16(unsigned daddr, const void* gptr, int srcsize){
    asm volatile("cp.async.cg.shared.global [%0], [%1], 16, %2;"
        :: "r"(daddr), "l"(gptr), "r"(srcsize));
}
__device__ __forceinline__ void cp_commit(){
    asm volatile("cp.async.commit_group;" ::: "memory");
}
__device__ __forceinline__ void cp_wait2(){
    asm volatile("cp.async.wait_group 2;" ::: "memory");
}

// paired emit:
// 0: C=v(float2) ; 1: Ch=half2(relu) ; 2: C=v & C2=relu ; 3: C=relu(aux)*sigmoid(v) ;
// 4: Ch=half2(v) ; 5: Ch=half2(v) & C=float2(relu(v))
__device__ __forceinline__ void emit2(float v0, float v1, size_t idx,
                                      float* C, float* C2, __half* Ch,
                                      const float* aux, int mode){
    if(mode == 0){
        *(float2*)(C + idx) = make_float2(v0, v1);
    } else if(mode == 1){
        *(__half2*)(Ch + idx) = __floats2half2_rn(fmaxf(v0,0.f), fmaxf(v1,0.f));
    } else if(mode == 2){
        *(float2*)(C  + idx) = make_float2(v0, v1);
        *(float2*)(C2 + idx) = make_float2(fmaxf(v0,0.f), fmaxf(v1,0.f));
    } else if(mode == 3){
        float2 a = *(const float2*)(aux + idx);
        float s0 = 1.f/(1.f + __expf(-v0));
        float s1 = 1.f/(1.f + __expf(-v1));
        *(float2*)(C + idx) = make_float2(fmaxf(a.x,0.f)*s0, fmaxf(a.y,0.f)*s1);
    } else if(mode == 4){
        *(__half2*)(Ch + idx) = __floats2half2_rn(v0, v1);
    } else {
        *(__half2*)(Ch + idx) = __floats2half2_rn(v0, v1);
        *(float2*)(C + idx)   = make_float2(fmaxf(v0,0.f), fmaxf(v1,0.f));
    }
}

// mode 6: fused combine epilogue
__global__ void __launch_bounds__(256, 2)
k_hgemm(int M, int Ncol, int K,
        const __half* __restrict__ A, int lda,
        const __half* __restrict__ W, int ldw,
        const float* __restrict__ bias,
        float* __restrict__ C, int ldc,
        float* __restrict__ C2, __half* __restrict__ Ch,
        const float* __restrict__ aux, int mode,
        const int* __restrict__ eidx, const int* __restrict__ revp,
        const __half* __restrict__ Xah, const __half* __restrict__ Xdh,
        const __half* __restrict__ ECh)
{
    extern __shared__ unsigned char smem_raw[];

    const int tid  = threadIdx.x;
    const int lane = tid & 31;
    const int warp = tid >> 5;
    const int tg   = lane & 3;
    const int g    = lane >> 2;
    const int bm   = blockIdx.y * 128;
    const int bn   = blockIdx.x * 128;
    const int mw   = (warp >> 2) * 64;
    const int nw   = (warp & 3) * 32;

    const unsigned sAaddr = (unsigned)__cvta_generic_to_shared(smem_raw);
    const unsigned sBaddr = sAaddr + STAGES*TWB;

    int cR[2], cK8[2];
    #pragma unroll
    for(int i=0;i<2;i++){
        int u = i*256 + tid;
        cR[i] = u >> 2; cK8[i] = (u & 3) << 3;
    }

    const int NC = K / 32;
    auto issue = [&](int kc, int buf){
        if(kc < NC){
            const int k0 = kc * 32;
            #pragma unroll
            for(int i=0;i<2;i++){
                unsigned doff = (unsigned)(buf*TWB + cR[i]*(RSH*2) + cK8[i]*2);
                int gm = bm + cR[i];
                const __half* srcA = A + (size_t)(gm < M ? gm : 0)*lda + k0 + cK8[i];
                cp16(sAaddr + doff, srcA, gm < M ? 16 : 0);
                const __half* srcB = W + (size_t)(bn + cR[i])*ldw + k0 + cK8[i];
                cp16(sBaddr + doff, srcB, 16);
            }
        }
        cp_commit();
    };

    const int lr  = lane & 15;
    const int lc8 = (lane >> 4) << 3;
    unsigned aOff[4], bOff[2];
    #pragma unroll
    for(int mi=0;mi<4;mi++)  aOff[mi]  = (unsigned)(((mw + mi*16 + lr)*RSH + lc8) * 2);
    #pragma unroll
    for(int ni2=0;ni2<2;ni2++) bOff[ni2] = (unsigned)(((nw + ni2*16 + lr)*RSH + lc8) * 2);

    float acc[4][4][4];
    #pragma unroll
    for(int mi=0;mi<4;mi++)
        #pragma unroll
        for(int ni=0;ni<4;ni++)
            #pragma unroll
            for(int t=0;t<4;t++) acc[mi][ni][t] = 0.f;

    issue(0, 0); issue(1, 1); issue(2, 2);

    int buf = 0;
    for(int c=0; c<NC; c++){
        cp_wait2();
        __syncthreads();

        issue(c + 3, (buf + 3) & 3);

        const unsigned aBase = sAaddr + (unsigned)(buf*TWB);
        const unsigned bBase = sBaddr + (unsigned)(buf*TWB);
        #pragma unroll
        for(int ks=0;ks<32;ks+=16){
            unsigned af[4][4], bf[4][2];
            #pragma unroll
            for(int mi=0;mi<4;mi++)
                ldsm4(af[mi][0], af[mi][1], af[mi][2], af[mi][3],
                      aBase + aOff[mi] + (unsigned)(ks*2));
            #pragma unroll
            for(int ni2=0;ni2<2;ni2++){
                unsigned r0,r1,r2,r3;
                ldsm4(r0, r1, r2, r3, bBase + bOff[ni2] + (unsigned)(ks*2));
                bf[ni2*2+0][0] = r0; bf[ni2*2+0][1] = r2;
                bf[ni2*2+1][0] = r1; bf[ni2*2+1][1] = r3;
            }
            #pragma unroll
            for(int mi=0;mi<4;mi++)
                #pragma unroll
                for(int ni=0;ni<4;ni++)
                    mma_f16(acc[mi][ni], af[mi], bf[ni]);
        }
        buf = (buf + 1) & 3;
    }

    // ---- epilogue
    if(mode == 6){
        #pragma unroll
        for(int mi=0;mi<4;mi++){
            #pragma unroll
            for(int rr2=0;rr2<2;rr2++){
                int row = bm + mw + mi*16 + g + rr2*8;
                if(row >= M) continue;
                int r  = eidx[row];
                int cc = eidx[M + row];
                int rv = revp[row];
                const __half* xaRow = Xah + (size_t)r *768;
                const __half* xdRow = Xdh + (size_t)cc*768;
                const __half* ecRow = (rv >= 0) ? (ECh + (size_t)rv*768) : nullptr;
                #pragma unroll
                for(int ni=0;ni<4;ni++){
                    int col = bn + nw + ni*8 + tg*2;
                    float v0 = acc[mi][ni][rr2*2+0] + bias[col];
                    float v1 = acc[mi][ni][rr2*2+1] + bias[col+1];
                    float2 xa = __half22float2(*(const __half2*)(xaRow + col));
                    float2 xd = __half22float2(*(const __half2*)(xdRow + col));
                    v0 += xa.x + xd.x; v1 += xa.y + xd.y;
                    if(ecRow){
                        float2 ec = __half22float2(*(const __half2*)(ecRow + col));
                        v0 += ec.x; v1 += ec.y;
                    }
                    *(__half2*)(Ch + (size_t)row*ldc + col) =
                        __floats2half2_rn(fmaxf(v0,0.f), fmaxf(v1,0.f));
                }
            }
        }
        return;
    }

    #pragma unroll
    for(int mi=0;mi<4;mi++){
        int row0 = bm + mw + mi*16 + g;
        int row1 = row0 + 8;
        #pragma unroll
        for(int ni=0;ni<4;ni++){
            int col = bn + nw + ni*8 + tg*2;
            float b0 = bias ? bias[col]   : 0.f;
            float b1 = bias ? bias[col+1] : 0.f;
            if(row0 < M)
                emit2(acc[mi][ni][0] + b0, acc[mi][ni][1] + b1,
                      (size_t)row0*ldc + col, C, C2, Ch, aux, mode);
            if(row1 < M)
                emit2(acc[mi][ni][2] + b0, acc[mi][ni][3] + b1,
                      (size_t)row1*ldc + col, C, C2, Ch, aux, mode);
        }
    }
}

// ---------------- attention layer-2 + softmax + weighted + scatter-max
// a1 = relu(Qa[r-pair] + Ka[e-pair]); att = a1 @ Wa2^T + ba2
__global__ void __launch_bounds__(256)
k_attn(const int* __restrict__ ei,
       const float* __restrict__ Wa2, const float* __restrict__ ba2,
       float* __restrict__ out_prob, int E)
{
    __shared__ float4 sW2[512];
    __shared__ float  sb2[32];
    for(int i=threadIdx.x;i<512;i+=256) sW2[i] = ((const float4*)Wa2)[i];
    if(threadIdx.x < 32) sb2[threadIdx.x] = ba2[threadIdx.x];
    __syncthreads();

    long long gid = (long long)blockIdx.x*256 + threadIdx.x;
    if(gid >= (long long)E*8) return;
    int e = (int)(gid >> 3);
    int h = (int)(gid & 7);
    int r = ei[e], c = ei[E+e];

    const uint4* qa4 = (const uint4*)(g_Qa + ((size_t)r*4 + (h>>1))*128 + (h&1)*64);
    const uint4* ka4 = (const uint4*)(g_Ka + ((size_t)e*4 + (h>>1))*128 + (h&1)*64);
    uint4 qa[8], ka[8];
    #pragma unroll
    for(int i=0;i<8;i++){ qa[i] = qa4[i]; ka[i] = ka4[i]; }
    const __half2* qh = (const __half2*)qa;
    const __half2* kh = (const __half2*)ka;

    float att[32];
    #pragma unroll
    for(int p=0;p<32;p++) att[p] = sb2[p];

    #pragma unroll 1
    for(int o4=0;o4<16;o4++){
        float a1v[4];
        #pragma unroll
        for(int j=0;j<2;j++){
            float2 fq = __half22float2(qh[o4*2+j]);
            float2 fk = __half22float2(kh[o4*2+j]);
            a1v[j*2+0] = fmaxf(fq.x + fk.x, 0.f);
            a1v[j*2+1] = fmaxf(fq.y + fk.y, 0.f);
        }
        #pragma unroll
        for(int p=0;p<32;p++){
            float4 w = sW2[p*16 + o4];
            att[p] += w.x*a1v[0] + w.y*a1v[1] + w.z*a1v[2] + w.w*a1v[3];
        }
    }

    const float invT = 0.17677669529663687f;
    float mx = att[0];
    #pragma unroll
    for(int p=1;p<32;p++) mx = fmaxf(mx, att[p]);
    float sum = 0.f;
    #pragma unroll
    for(int p=0;p<32;p++){ att[p] = __expf((att[p]-mx)*invT); sum += att[p]; }
    float inv = 1.f/sum;

    float* pp = out_prob + (size_t)e*256 + h;
    const float* vrow = g_Vn + (size_t)c*256 + h;
    int* ar = g_aggI + r*256 + h;
    #pragma unroll
    for(int p=0;p<32;p++){
        float pr = att[p]*inv;
        pp[p*8] = pr;
        float w = pr * vrow[p*8];
        atomicMax(ar + p*8, f2oi(w));
    }
}

// ---------------- small elementwise kernels ----------------
__global__ void k_concat(const float* __restrict__ x, int N){
    int i = blockIdx.x*blockDim.x + threadIdx.x;
    if(i >= N*512) return;
    int n = i >> 9, j = i & 511;
    float v;
    if(j < 256){
        v = x[(size_t)n*256 + j];
    } else {
        float a = oi2f(g_aggI[(size_t)n*256 + j - 256]);
        v = isfinite(a) ? a : 0.f;
    }
    g_cat[i] = __float2half_rn(v);
}

__global__ void k_twin_scatter(const int* __restrict__ ei, int E){
    long long gid = (long long)blockIdx.x*blockDim.x + threadIdx.x;
    if(gid >= (long long)E*64) return;
    int e  = (int)(gid >> 6);
    int j4 = (int)(gid & 63);
    int r = ei[e], c = ei[E+e];
    uint2 uu = *(const uint2*)(g_upe + (size_t)e*256 + j4*4);
    float2 u0 = __half22float2(*(__half2*)&uu.x);
    float2 u1 = __half22float2(*(__half2*)&uu.y);
    int base = j4*4;
    atomicAdd(&g_osum[r*256+base+0], u0.x);
    atomicAdd(&g_osum[r*256+base+1], u0.y);
    atomicAdd(&g_osum[r*256+base+2], u1.x);
    atomicAdd(&g_osum[r*256+base+3], u1.y);
    atomicAdd(&g_isum[c*256+base+0], u0.x);
    atomicAdd(&g_isum[c*256+base+1], u0.y);
    atomicAdd(&g_isum[c*256+base+2], u1.x);
    atomicAdd(&g_isum[c*256+base+3], u1.y);
}

__global__ void k_twin_final(int N){
    int i = blockIdx.x*blockDim.x + threadIdx.x;
    if(i >= N*512) return;
    int n = i >> 9, j = i & 511;
    float v;
    if(j < 256) v = g_osum[n*256 + j]       / fmaxf((float)g_ocnt[n], 1.f);
    else        v = g_isum[n*256 + j - 256] / fmaxf((float)g_icnt[n], 1.f);
    g_twin[i] = __float2half_rn(v);
}

// ---------------- launcher ----------------
extern "C" void kernel_launch(void* const* d_in, const int* in_sizes, int n_in,
                              void* d_out, int out_size)
{
    const float* x   = (const float*)d_in[0];
    const float* ea  = (const float*)d_in[1];
    const float* Wq  = (const float*)d_in[2];
    const float* bq  = (const float*)d_in[3];
    const float* Wk  = (const float*)d_in[4];
    const float* bk  = (const float*)d_in[5];
    const float* Wv  = (const float*)d_in[6];
    const float* bv  = (const float*)d_in[7];
    const float* We1 = (const float*)d_in[8];
    const float* be1 = (const float*)d_in[9];
    const float* We2 = (const float*)d_in[10];
    const float* be2 = (const float*)d_in[11];
    const float* Wea = (const float*)d_in[12];
    const float* bea = (const float*)d_in[13];
    const float* Wn1 = (const float*)d_in[14];
    const float* bn1 = (const float*)d_in[15];
    const float* Wn2 = (const float*)d_in[16];
    const float* bn2 = (const float*)d_in[17];
    const float* Wa1 = (const float*)d_in[18];
    const float* ba1 = (const float*)d_in[19];
    const float* Wa2 = (const float*)d_in[20];
    const float* ba2 = (const float*)d_in[21];
    const int*   ei  = (const int*)  d_in[22];

    const int N = in_sizes[0]/256;
    const int E = in_sizes[1]/256;

    float* out      = (float*)d_out;
    float* out_node = out;
    float* out_edge = out + (size_t)N*256;
    float* out_prob = out_edge + (size_t)E*256;

    void* p;
    #define GSYMF(v, s) float* v; cudaGetSymbolAddress(&p, s); v = (float*)p;
    #define GSYMI(v, s) int* v; cudaGetSymbolAddress(&p, s); v = (int*)p;
    #define GSYMH(v, s) __half* v; cudaGetSymbolAddress(&p, s); v = (__half*)p;
    GSYMF(pV,   g_Vn)  GSYMF(pUpn, g_upn)
    GSYMF(pBqp, g_bqp) GSYMF(pBkp, g_bkp) GSYMF(pB1d, g_b1d)
    GSYMI(pRev, g_rev)
    GSYMH(pUPE, g_upe)
    GSYMH(pXa,  g_Xa)  GSYMH(pXd,  g_Xd)  GSYMH(pEC, g_EC)
    GSYMH(pH,   g_hbuf)
    GSYMH(pCat, g_cat) GSYMH(pHn, g_hn)  GSYMH(pTwin, g_twin)
    GSYMH(pXr,  g_xr)  GSYMH(pEar, g_ear)
    GSYMH(pQh,  g_Qh)  GSYMH(pKh,  g_Kh)
    GSYMH(pQa,  g_Qa)  GSYMH(pKa,  g_Ka)
    GSYMH(pW1a, g_W1a) GSYMH(pW1b, g_W1b)
    GSYMH(pWe1h, g_We1h) GSYMH(pWe2h, g_We2h)
    GSYMH(pWqh, g_Wqh) GSYMH(pWkh, g_Wkh) GSYMH(pWvh, g_Wvh)
    GSYMH(pWn1h, g_Wn1h) GSYMH(pWn2h, g_Wn2h) GSYMH(pWeah, g_Weah)
    #undef GSYMF
    #undef GSYMI
    #undef GSYMH

    cudaFuncSetAttribute(k_hgemm, cudaFuncAttributeMaxDynamicSharedMemorySize, SMEM_BYTES);

    auto H = [&](const float* src, __half* dst, int n){
        k_tohalf<<<(n/4 + 255)/256, 256>>>((const float4*)src, (uint2*)dst, n/4);
    };
    auto GEMM = [&](int M, int Nc, int K, const __half* A, int lda,
                    const __half* W, int ldw, const float* bias,
                    float* C, int ldc, float* C2, __half* Ch,
                    const float* aux, int mode,
                    const int* eidx = nullptr, const int* revp = nullptr,
                    const __half* Xah = nullptr, const __half* Xdh = nullptr,
                    const __half* ECh = nullptr){
        dim3 g(Nc/128, (M+127)/128);
        k_hgemm<<<g, 256, SMEM_BYTES>>>(M, Nc, K, A, lda, W, ldw, bias,
                                        C, ldc, C2, Ch, aux, mode,
                                        eidx, revp, Xah, Xdh, ECh);
    };

    // order chosen so launch index 5 is a real GEMM (ncu -s 5)
    k_init<<<(NN*256+255)/256, 256>>>(N);
    k_hash_insert<<<(E+255)/256, 256>>>(ei, E, N);
    k_rev<<<(E+255)/256, 256>>>(ei, E, N);
    H(x,   pXr,   N*256);
    H(We1, pWe1h, 768*1024);
    GEMM(N, 768, 256, pXr,  256, pWe1h + 0,   1024, nullptr, nullptr, 768, nullptr, pXa, nullptr, 4);
    GEMM(N, 768, 256, pXr,  256, pWe1h + 768, 1024, nullptr, nullptr, 768, nullptr, pXd, nullptr, 4);
    H(ea,  pEar,  E*256);
    GEMM(E, 768, 256, pEar, 256, pWe1h + 512, 1024, nullptr, nullptr, 768, nullptr, pEC, nullptr, 4);
    GEMM(E, 768, 256, pEar, 256, pWe1h + 256, 1024, be1, nullptr, 768, nullptr, pH, nullptr, 6,
         ei, pRev, pXa, pXd, pEC);
    H(We2, pWe2h, 256*768);
    GEMM(E, 256, 768, pH, 768, pWe2h, 768, be2, out_edge, 256, nullptr, pUPE, nullptr, 5);

    // q/k head-major (half out), v fp32
    k_permqk<<<(256*64 + 255)/256, 256>>>(Wq, pWqh);
    k_permqk<<<(256*64 + 255)/256, 256>>>(Wk, pWkh);
    k_permbias<<<1, 256>>>(bq, bk);
    H(Wv,  pWvh,  256*256);
    GEMM(N, 256, 256, pXr,  256, pWqh, 256, pBqp, nullptr, 256, nullptr, pQh, nullptr, 4);
    GEMM(E, 256, 256, pEar, 256, pWkh, 256, pBkp, nullptr, 256, nullptr, pKh, nullptr, 4);
    GEMM(N, 256, 256, pXr,  256, pWvh, 256, bv,   pV, 256, nullptr, nullptr, nullptr, 0);

    // attention layer-1 on tensor cores (two heads per row, block-diag weights)
    k_prepw1<<<(128*64 + 255)/256, 256>>>(Wa1, ba1);
    GEMM(N*4, 128, 64, pQh, 64, pW1a, 64, pB1d,   nullptr, 128, nullptr, pQa, nullptr, 4);
    GEMM(E*4, 128, 64, pKh, 64, pW1b, 64, nullptr, nullptr, 128, nullptr, pKa, nullptr, 4);

    // attention layer-2 + softmax + scatter-max
    k_attn<<<(int)(((long long)E*8 + 255)/256), 256>>>(ei, Wa2, ba2, out_prob, E);

    // node update MLP
    H(Wn1, pWn1h, 512*512);
    H(Wn2, pWn2h, 256*512);
    H(Wea, pWeah, 256*512);
    k_concat<<<(NN*512+255)/256, 256>>>(x, N);
    GEMM(N, 512, 512, pCat, 512, pWn1h, 512, bn1, nullptr, 512, nullptr, pHn, nullptr, 1);
    GEMM(N, 256, 512, pHn,  512, pWn2h, 512, bn2, pUpn, 256, nullptr, nullptr, nullptr, 0);

    // twin aggregation + gated output
    k_twin_scatter<<<(int)(((long long)E*64 + 255)/256), 256>>>(ei, E);
    k_twin_final<<<(NN*512+255)/256, 256>>>(N);
    GEMM(N, 256, 512, pTwin, 512, pWeah, 512, bea, out_node, 256, nullptr, nullptr, pUpn, 3);
}